// round 4
// baseline (speedup 1.0000x reference)
#include <cuda_runtime.h>
#include <math.h>
#include <math_constants.h>

#define HIDDEN 768
#define NHEAD  12
#define HD     64
#define BATCH  8
#define NTOK   1024
#define C_IN   256
#define M_TOT  (BATCH * NTOK)

// ---------------- scratch (static device arrays; no allocation) ----------------
__device__ float d_tokens[M_TOT * HIDDEN];
__device__ float d_q[M_TOT * HIDDEN];
__device__ float d_k[M_TOT * HIDDEN];
__device__ float d_v[M_TOT * HIDDEN];
__device__ float d_attn[M_TOT * HIDDEN];
__device__ float d_g[M_TOT];
__device__ float d_pe[NTOK * HIDDEN];

// ---------------- positional encoding (double precision for fidelity) ----------
__global__ void pe_kernel() {
    int idx = blockIdx.x * blockDim.x + threadIdx.x;
    if (idx >= NTOK * HIDDEN) return;
    int n = idx / HIDDEN, d = idx % HIDDEN;
    int i2 = d & ~1;  // 2*(d/2)
    double div = exp(-(double)i2 * 9.210340371976184 / 768.0);
    double ph = (double)n * div;
    d_pe[idx] = (float)((d & 1) ? cos(ph) : sin(ph));
}

// ---------------- gaussian weights -----------------------------------------
__global__ void gauss_kernel(const float* __restrict__ I) {
    int idx = blockIdx.x * blockDim.x + threadIdx.x;
    if (idx >= M_TOT) return;
    float x = I[idx];
    float x2 = x * x;
    const float d0 = 2.0f * 0.25f + 1e-5f;   // k=0.5
    const float d1 = 2.0f * 1.00f + 1e-5f;   // k=1
    const float d2 = 2.0f * 4.00f + 1e-5f;   // k=2
    float g = (expf(-x2 / d0) + expf(-x2 / d1) + expf(-x2 / d2)) * (1.0f / 3.0f);
    d_g[idx] = g;
}

// ---------------- projection: tokens[b,n,d] = sum_c feat[b,c,n]*pw[c,d] + pb + pe
__global__ void proj_kernel(const float* __restrict__ feat,
                            const float* __restrict__ pw,
                            const float* __restrict__ pb) {
    __shared__ float As[16 * 68];   // As[k][i]  (k = c-chunk, i = n within tile)
    __shared__ float Bs[16 * 68];   // Bs[k][j]  (j = d within tile)
    int tid = threadIdx.x;
    int tx = tid & 15, ty = tid >> 4;
    int d0 = blockIdx.x * 64;
    int n0 = blockIdx.y * 64;
    int b  = blockIdx.z;
    const float* featb = feat + (size_t)b * C_IN * NTOK;
    float acc[4][4] = {};

    for (int c0 = 0; c0 < C_IN; c0 += 16) {
        #pragma unroll
        for (int p = 0; p < 4; p++) {
            int i = tid & 63;
            int k = (tid >> 6) + p * 4;
            As[k * 68 + i] = featb[(size_t)(c0 + k) * NTOK + n0 + i];
        }
        #pragma unroll
        for (int p = 0; p < 4; p++) {
            int j = tid & 63;
            int k = (tid >> 6) + p * 4;
            Bs[k * 68 + j] = pw[(size_t)(c0 + k) * HIDDEN + d0 + j];
        }
        __syncthreads();
        #pragma unroll
        for (int kk = 0; kk < 16; kk++) {
            float4 av = *(const float4*)(As + kk * 68 + ty * 4);
            float4 bv = *(const float4*)(Bs + kk * 68 + tx * 4);
            float a[4] = {av.x, av.y, av.z, av.w};
            float bb[4] = {bv.x, bv.y, bv.z, bv.w};
            #pragma unroll
            for (int i = 0; i < 4; i++)
                #pragma unroll
                for (int j = 0; j < 4; j++)
                    acc[i][j] += a[i] * bb[j];
        }
        __syncthreads();
    }
    #pragma unroll
    for (int i = 0; i < 4; i++) {
        int n = n0 + ty * 4 + i;
        int dd = d0 + tx * 4;
        const float* pe = d_pe + (size_t)n * HIDDEN + dd;
        float4 o;
        o.x = acc[i][0] + pb[dd + 0] + pe[0];
        o.y = acc[i][1] + pb[dd + 1] + pe[1];
        o.z = acc[i][2] + pb[dd + 2] + pe[2];
        o.w = acc[i][3] + pb[dd + 3] + pe[3];
        *(float4*)&d_tokens[((size_t)b * NTOK + n) * HIDDEN + dd] = o;
    }
}

// ---------------- generic 768-K GEMM: C = A[M,768] @ W[768,768] + bias --------
// QKV==1: output written in [b, h, n, hd] layout; QKV==0: row-major [M,768]
template <int QKV>
__global__ void gemm768_kernel(const float* __restrict__ A,
                               const float* __restrict__ W,
                               const float* __restrict__ bias,
                               float* __restrict__ Cout) {
    __shared__ float As[16 * 68];  // As[k][i]
    __shared__ float Bs[16 * 68];  // Bs[k][j]
    int tid = threadIdx.x;
    int tx = tid & 15, ty = tid >> 4;
    int n0 = blockIdx.x * 64;
    int m0 = blockIdx.y * 64;
    float acc[4][4] = {};

    for (int k0 = 0; k0 < HIDDEN; k0 += 16) {
        #pragma unroll
        for (int p = 0; p < 4; p++) {
            int k = tid & 15;
            int i = (tid >> 4) + p * 16;
            As[k * 68 + i] = A[(size_t)(m0 + i) * HIDDEN + k0 + k];
        }
        #pragma unroll
        for (int p = 0; p < 4; p++) {
            int j = tid & 63;
            int k = (tid >> 6) + p * 4;
            Bs[k * 68 + j] = W[(size_t)(k0 + k) * HIDDEN + n0 + j];
        }
        __syncthreads();
        #pragma unroll
        for (int kk = 0; kk < 16; kk++) {
            float4 av = *(const float4*)(As + kk * 68 + ty * 4);
            float4 bv = *(const float4*)(Bs + kk * 68 + tx * 4);
            float a[4] = {av.x, av.y, av.z, av.w};
            float bb[4] = {bv.x, bv.y, bv.z, bv.w};
            #pragma unroll
            for (int i = 0; i < 4; i++)
                #pragma unroll
                for (int j = 0; j < 4; j++)
                    acc[i][j] += a[i] * bb[j];
        }
        __syncthreads();
    }
    #pragma unroll
    for (int i = 0; i < 4; i++) {
        int m = m0 + ty * 4 + i;
        int j0 = n0 + tx * 4;
        float4 o;
        o.x = acc[i][0] + bias[j0 + 0];
        o.y = acc[i][1] + bias[j0 + 1];
        o.z = acc[i][2] + bias[j0 + 2];
        o.w = acc[i][3] + bias[j0 + 3];
        if (QKV) {
            int b = m >> 10, n = m & 1023;
            int h = j0 >> 6, dd = j0 & 63;
            *(float4*)&Cout[(((size_t)(b * NHEAD + h) * NTOK) + n) * HD + dd] = o;
        } else {
            *(float4*)&Cout[(size_t)m * HIDDEN + j0] = o;
        }
    }
}

// ---------------- flash attention: per (b,h), 64-row q-tile --------------------
// scores = QK^T/8 + lam*g_q*g_k ; online softmax ; out = P V
__global__ void attn_kernel(const float* __restrict__ lam_p) {
    extern __shared__ float sm[];
    float* Qt  = sm;              // [64 k][68] : Qt[k][r]
    float* Kt  = Qt + 64 * 68;    // [64 k][68] : Kt[k][c]
    float* Vs  = Kt + 64 * 68;    // [64 c][68] : Vs[c][d]
    float* St  = Vs + 64 * 68;    // [64 c][68] : St[c][r]  (scores transposed)
    float* msh = St + 64 * 68;
    float* lsh = msh + 64;
    float* ash = lsh + 64;
    float* gq  = ash + 64;
    float* gk  = gq + 64;

    int tid = threadIdx.x;
    int tx = tid & 15, ty = tid >> 4;
    int n0 = blockIdx.x * 64;
    int h  = blockIdx.y;
    int b  = blockIdx.z;
    const float lam = *lam_p;
    size_t base = (size_t)(b * NHEAD + h) * NTOK * HD;

    for (int idx = tid; idx < 64 * 64; idx += 256) {
        int r = idx >> 6, k = idx & 63;
        Qt[k * 68 + r] = d_q[base + (size_t)(n0 + r) * HD + k];
    }
    if (tid < 64) {
        msh[tid] = -CUDART_INF_F;
        lsh[tid] = 0.0f;
        gq[tid]  = d_g[b * NTOK + n0 + tid];
    }

    float o[4][4] = {};
    for (int k0 = 0; k0 < NTOK; k0 += 64) {
        __syncthreads();
        for (int idx = tid; idx < 64 * 64; idx += 256) {
            int c = idx >> 6, k = idx & 63;
            float kval = d_k[base + (size_t)(k0 + c) * HD + k];
            float vval = d_v[base + (size_t)(k0 + c) * HD + k];
            Kt[k * 68 + c] = kval;
            Vs[c * 68 + k] = vval;
        }
        if (tid < 64) gk[tid] = d_g[b * NTOK + k0 + tid];
        __syncthreads();

        // GEMM1: s = Q K^T
        float s[4][4] = {};
        #pragma unroll
        for (int kk = 0; kk < 64; kk++) {
            float4 qv = *(const float4*)(Qt + kk * 68 + ty * 4);
            float4 kv = *(const float4*)(Kt + kk * 68 + tx * 4);
            float a[4] = {qv.x, qv.y, qv.z, qv.w};
            float bb[4] = {kv.x, kv.y, kv.z, kv.w};
            #pragma unroll
            for (int i = 0; i < 4; i++)
                #pragma unroll
                for (int j = 0; j < 4; j++)
                    s[i][j] += a[i] * bb[j];
        }
        // scale + gaussian bias; store transposed
        #pragma unroll
        for (int i = 0; i < 4; i++) {
            float gqi = gq[ty * 4 + i];
            #pragma unroll
            for (int j = 0; j < 4; j++) {
                float v = s[i][j] * 0.125f + lam * gqi * gk[tx * 4 + j];
                St[(tx * 4 + j) * 68 + ty * 4 + i] = v;
            }
        }
        __syncthreads();

        // online softmax (64 threads, one per query row)
        if (tid < 64) {
            int r = tid;
            float m_old = msh[r];
            float mx = m_old;
            for (int c = 0; c < 64; c++) mx = fmaxf(mx, St[c * 68 + r]);
            float alpha = expf(m_old - mx);
            float sum = 0.0f;
            for (int c = 0; c < 64; c++) {
                float p = expf(St[c * 68 + r] - mx);
                St[c * 68 + r] = p;
                sum += p;
            }
            msh[r] = mx;
            lsh[r] = lsh[r] * alpha + sum;
            ash[r] = alpha;
        }
        __syncthreads();

        float al[4];
        #pragma unroll
        for (int i = 0; i < 4; i++) al[i] = ash[ty * 4 + i];
        #pragma unroll
        for (int i = 0; i < 4; i++)
            #pragma unroll
            for (int j = 0; j < 4; j++)
                o[i][j] *= al[i];

        // GEMM2: o += P V
        #pragma unroll
        for (int c = 0; c < 64; c++) {
            float4 pv = *(const float4*)(St + c * 68 + ty * 4);
            float4 vv = *(const float4*)(Vs + c * 68 + tx * 4);
            float p[4] = {pv.x, pv.y, pv.z, pv.w};
            float vvv[4] = {vv.x, vv.y, vv.z, vv.w};
            #pragma unroll
            for (int i = 0; i < 4; i++)
                #pragma unroll
                for (int j = 0; j < 4; j++)
                    o[i][j] += p[i] * vvv[j];
        }
    }

    float linv[4];
    #pragma unroll
    for (int i = 0; i < 4; i++) linv[i] = 1.0f / lsh[ty * 4 + i];
    #pragma unroll
    for (int i = 0; i < 4; i++) {
        int n = n0 + ty * 4 + i;
        float4 ov;
        ov.x = o[i][0] * linv[i];
        ov.y = o[i][1] * linv[i];
        ov.z = o[i][2] * linv[i];
        ov.w = o[i][3] * linv[i];
        *(float4*)&d_attn[((size_t)b * NTOK + n) * HIDDEN + h * HD + tx * 4] = ov;
    }
}

// ---------------- launch --------------------------------------------------------
extern "C" void kernel_launch(void* const* d_in, const int* in_sizes, int n_in,
                              void* d_out, int out_size) {
    const float* feat = (const float*)d_in[0];
    const float* I    = (const float*)d_in[1];
    const float* pw   = (const float*)d_in[2];
    const float* pb   = (const float*)d_in[3];
    const float* wq   = (const float*)d_in[4];
    const float* bq   = (const float*)d_in[5];
    const float* wk   = (const float*)d_in[6];
    const float* bk   = (const float*)d_in[7];
    const float* wv   = (const float*)d_in[8];
    const float* bv   = (const float*)d_in[9];
    const float* wo   = (const float*)d_in[10];
    const float* bo   = (const float*)d_in[11];
    const float* lam  = (const float*)d_in[12];
    float* out = (float*)d_out;

    float *tok, *q, *k, *v, *attn;
    cudaGetSymbolAddress((void**)&tok,  d_tokens);
    cudaGetSymbolAddress((void**)&q,    d_q);
    cudaGetSymbolAddress((void**)&k,    d_k);
    cudaGetSymbolAddress((void**)&v,    d_v);
    cudaGetSymbolAddress((void**)&attn, d_attn);

    // positional encoding + gaussian weights
    pe_kernel<<<(NTOK * HIDDEN + 255) / 256, 256>>>();
    gauss_kernel<<<(M_TOT + 255) / 256, 256>>>(I);

    // projection
    proj_kernel<<<dim3(HIDDEN / 64, NTOK / 64, BATCH), 256>>>(feat, pw, pb);

    // QKV GEMMs (write [b,h,n,d])
    dim3 gQKV(HIDDEN / 64, M_TOT / 64);
    gemm768_kernel<1><<<gQKV, 256>>>(tok, wq, bq, q);
    gemm768_kernel<1><<<gQKV, 256>>>(tok, wk, bk, k);
    gemm768_kernel<1><<<gQKV, 256>>>(tok, wv, bv, v);

    // attention
    size_t smem = (4 * 64 * 68 + 5 * 64) * sizeof(float);  // 70912 B
    cudaFuncSetAttribute(attn_kernel, cudaFuncAttributeMaxDynamicSharedMemorySize,
                         (int)smem);
    attn_kernel<<<dim3(NTOK / 64, NHEAD, BATCH), 256, smem>>>(lam);

    // output projection
    gemm768_kernel<0><<<gQKV, 256>>>(attn, wo, bo, out);
}

// round 6
// speedup vs baseline: 1.1715x; 1.1715x over previous
#include <cuda_runtime.h>
#include <math.h>
#include <math_constants.h>

#define HIDDEN 768
#define NHEAD  12
#define HD     64
#define BATCH  8
#define NTOK   1024
#define C_IN   256
#define M_TOT  (BATCH * NTOK)

// ---------------- scratch (static device arrays; no allocation) ----------------
__device__ float d_tokens[M_TOT * HIDDEN];
__device__ float d_q[M_TOT * HIDDEN];
__device__ float d_k[M_TOT * HIDDEN];
__device__ float d_v[M_TOT * HIDDEN];
__device__ float d_attn[M_TOT * HIDDEN];
__device__ float d_g[M_TOT];
__device__ float d_pe[NTOK * HIDDEN];

// ---------------- positional encoding (fp32 — DP was a hidden time sink) -------
__global__ void pe_kernel() {
    int idx = blockIdx.x * blockDim.x + threadIdx.x;
    if (idx >= NTOK * HIDDEN) return;
    int n = idx / HIDDEN, d = idx % HIDDEN;
    int i2 = d & ~1;  // 2*(d/2)
    float div = expf((float)i2 * -0.011992630692677323f);  // -ln(10000)/768
    float ph = (float)n * div;
    d_pe[idx] = (d & 1) ? cosf(ph) : sinf(ph);
}

// ---------------- gaussian weights ---------------------------------------------
__global__ void gauss_kernel(const float* __restrict__ I) {
    int idx = blockIdx.x * blockDim.x + threadIdx.x;
    if (idx >= M_TOT) return;
    float x = I[idx];
    float x2 = x * x;
    const float d0 = 2.0f * 0.25f + 1e-5f;
    const float d1 = 2.0f * 1.00f + 1e-5f;
    const float d2 = 2.0f * 4.00f + 1e-5f;
    float g = (expf(-x2 / d0) + expf(-x2 / d1) + expf(-x2 / d2)) * (1.0f / 3.0f);
    d_g[idx] = g;
}

// ================= 128x128x16 double-buffered fp32 GEMM (8x8 microtile) ========
// C[M,768] = A[M,768] @ W[768,768] + bias.  QKV==1: write [b,h,n,hd] layout.
template <int QKV>
__global__ __launch_bounds__(256, 2)
void gemm128_kernel(const float* __restrict__ A, const float* __restrict__ W,
                    const float* __restrict__ bias, float* __restrict__ Cout) {
    __shared__ float As[2][16][128];   // As[buf][k][m]
    __shared__ float Bs[2][16][128];   // Bs[buf][k][n]
    const int tid = threadIdx.x;
    const int tx = tid & 15, ty = tid >> 4;
    const int n0 = blockIdx.x * 128;
    const int m0 = blockIdx.y * 128;

    // A tile loader: rows ar, ar+64; cols ac..ac+3 (transposed into As)
    const int ar = tid >> 2;            // 0..63
    const int ac = (tid & 3) << 2;      // 0,4,8,12
    // B tile loader: rows brw, brw+8; cols bcl..bcl+3 (direct)
    const int brw = tid >> 5;           // 0..7
    const int bcl = (tid & 31) << 2;    // 0..124

    const float* Ap0 = A + (size_t)(m0 + ar) * HIDDEN + ac;
    const float* Ap1 = Ap0 + (size_t)64 * HIDDEN;
    const float* Wp0 = W + (size_t)brw * HIDDEN + n0 + bcl;
    const float* Wp1 = Wp0 + (size_t)8 * HIDDEN;

    float4 a0 = *(const float4*)Ap0;
    float4 a1 = *(const float4*)Ap1;
    float4 b0 = *(const float4*)Wp0;
    float4 b1 = *(const float4*)Wp1;

    float acc[8][8];
    #pragma unroll
    for (int i = 0; i < 8; i++)
        #pragma unroll
        for (int j = 0; j < 8; j++) acc[i][j] = 0.0f;

    // store tile 0
    As[0][ac + 0][ar] = a0.x; As[0][ac + 1][ar] = a0.y;
    As[0][ac + 2][ar] = a0.z; As[0][ac + 3][ar] = a0.w;
    As[0][ac + 0][64 + ar] = a1.x; As[0][ac + 1][64 + ar] = a1.y;
    As[0][ac + 2][64 + ar] = a1.z; As[0][ac + 3][64 + ar] = a1.w;
    *(float4*)&Bs[0][brw][bcl] = b0;
    *(float4*)&Bs[0][brw + 8][bcl] = b1;

    int buf = 0;
    #pragma unroll 1
    for (int t = 0; t < 48; t++) {
        if (t < 47) {  // prefetch next k-slab into registers
            a0 = *(const float4*)(Ap0 + (t + 1) * 16);
            a1 = *(const float4*)(Ap1 + (t + 1) * 16);
            b0 = *(const float4*)(Wp0 + (size_t)(t + 1) * 16 * HIDDEN);
            b1 = *(const float4*)(Wp1 + (size_t)(t + 1) * 16 * HIDDEN);
        }
        __syncthreads();
        #pragma unroll
        for (int kk = 0; kk < 16; kk++) {
            float4 x0 = *(const float4*)&As[buf][kk][ty << 2];
            float4 x1 = *(const float4*)&As[buf][kk][64 + (ty << 2)];
            float4 y0 = *(const float4*)&Bs[buf][kk][tx << 2];
            float4 y1 = *(const float4*)&Bs[buf][kk][64 + (tx << 2)];
            float xa[8] = {x0.x, x0.y, x0.z, x0.w, x1.x, x1.y, x1.z, x1.w};
            float yb[8] = {y0.x, y0.y, y0.z, y0.w, y1.x, y1.y, y1.z, y1.w};
            #pragma unroll
            for (int i = 0; i < 8; i++)
                #pragma unroll
                for (int j = 0; j < 8; j++)
                    acc[i][j] += xa[i] * yb[j];
        }
        if (t < 47) {
            int nb = buf ^ 1;
            As[nb][ac + 0][ar] = a0.x; As[nb][ac + 1][ar] = a0.y;
            As[nb][ac + 2][ar] = a0.z; As[nb][ac + 3][ar] = a0.w;
            As[nb][ac + 0][64 + ar] = a1.x; As[nb][ac + 1][64 + ar] = a1.y;
            As[nb][ac + 2][64 + ar] = a1.z; As[nb][ac + 3][64 + ar] = a1.w;
            *(float4*)&Bs[nb][brw][bcl] = b0;
            *(float4*)&Bs[nb][brw + 8][bcl] = b1;
        }
        buf ^= 1;
    }

    #pragma unroll
    for (int ih = 0; ih < 2; ih++)
        #pragma unroll
        for (int i = 0; i < 4; i++) {
            int m = m0 + ih * 64 + (ty << 2) + i;
            #pragma unroll
            for (int jh = 0; jh < 2; jh++) {
                int j0 = n0 + jh * 64 + (tx << 2);
                float4 o;
                o.x = acc[ih * 4 + i][jh * 4 + 0] + bias[j0 + 0];
                o.y = acc[ih * 4 + i][jh * 4 + 1] + bias[j0 + 1];
                o.z = acc[ih * 4 + i][jh * 4 + 2] + bias[j0 + 2];
                o.w = acc[ih * 4 + i][jh * 4 + 3] + bias[j0 + 3];
                if (QKV) {
                    int b = m >> 10, nn = m & 1023;
                    int h = j0 >> 6, dd = j0 & 63;
                    *(float4*)&Cout[(((size_t)(b * NHEAD + h) * NTOK) + nn) * HD + dd] = o;
                } else {
                    *(float4*)&Cout[(size_t)m * HIDDEN + j0] = o;
                }
            }
        }
}

// ================= projection: tokens = feat^T @ pw + pb + pe ==================
// feat is [B, C, N] (K-major for this GEMM) so As fills are direct float4 copies.
__global__ __launch_bounds__(256, 2)
void proj128_kernel(const float* __restrict__ feat, const float* __restrict__ pw,
                    const float* __restrict__ pb) {
    __shared__ float As[2][16][128];   // As[buf][k(c)][m(n)]
    __shared__ float Bs[2][16][128];   // Bs[buf][k(c)][n(d)]
    const int tid = threadIdx.x;
    const int tx = tid & 15, ty = tid >> 4;
    const int d0 = blockIdx.x * 128;
    const int n0 = blockIdx.y * 128;
    const int b  = blockIdx.z;
    const float* fb = feat + (size_t)b * C_IN * NTOK;

    const int akr = tid >> 5;           // 0..7
    const int am4 = (tid & 31) << 2;    // 0..124
    const int brw = tid >> 5;
    const int bcl = (tid & 31) << 2;

    const float* Fp0 = fb + (size_t)akr * NTOK + n0 + am4;
    const float* Fp1 = Fp0 + (size_t)8 * NTOK;
    const float* Wp0 = pw + (size_t)brw * HIDDEN + d0 + bcl;
    const float* Wp1 = Wp0 + (size_t)8 * HIDDEN;

    float4 a0 = *(const float4*)Fp0;
    float4 a1 = *(const float4*)Fp1;
    float4 b0 = *(const float4*)Wp0;
    float4 b1 = *(const float4*)Wp1;

    float acc[8][8];
    #pragma unroll
    for (int i = 0; i < 8; i++)
        #pragma unroll
        for (int j = 0; j < 8; j++) acc[i][j] = 0.0f;

    *(float4*)&As[0][akr][am4] = a0;
    *(float4*)&As[0][akr + 8][am4] = a1;
    *(float4*)&Bs[0][brw][bcl] = b0;
    *(float4*)&Bs[0][brw + 8][bcl] = b1;

    int buf = 0;
    #pragma unroll 1
    for (int t = 0; t < 16; t++) {   // K = 256 = 16*16
        if (t < 15) {
            a0 = *(const float4*)(Fp0 + (size_t)(t + 1) * 16 * NTOK);
            a1 = *(const float4*)(Fp1 + (size_t)(t + 1) * 16 * NTOK);
            b0 = *(const float4*)(Wp0 + (size_t)(t + 1) * 16 * HIDDEN);
            b1 = *(const float4*)(Wp1 + (size_t)(t + 1) * 16 * HIDDEN);
        }
        __syncthreads();
        #pragma unroll
        for (int kk = 0; kk < 16; kk++) {
            float4 x0 = *(const float4*)&As[buf][kk][ty << 2];
            float4 x1 = *(const float4*)&As[buf][kk][64 + (ty << 2)];
            float4 y0 = *(const float4*)&Bs[buf][kk][tx << 2];
            float4 y1 = *(const float4*)&Bs[buf][kk][64 + (tx << 2)];
            float xa[8] = {x0.x, x0.y, x0.z, x0.w, x1.x, x1.y, x1.z, x1.w};
            float yb[8] = {y0.x, y0.y, y0.z, y0.w, y1.x, y1.y, y1.z, y1.w};
            #pragma unroll
            for (int i = 0; i < 8; i++)
                #pragma unroll
                for (int j = 0; j < 8; j++)
                    acc[i][j] += xa[i] * yb[j];
        }
        if (t < 15) {
            int nb = buf ^ 1;
            *(float4*)&As[nb][akr][am4] = a0;
            *(float4*)&As[nb][akr + 8][am4] = a1;
            *(float4*)&Bs[nb][brw][bcl] = b0;
            *(float4*)&Bs[nb][brw + 8][bcl] = b1;
        }
        buf ^= 1;
    }

    #pragma unroll
    for (int ih = 0; ih < 2; ih++)
        #pragma unroll
        for (int i = 0; i < 4; i++) {
            int n = n0 + ih * 64 + (ty << 2) + i;
            #pragma unroll
            for (int jh = 0; jh < 2; jh++) {
                int j0 = d0 + jh * 64 + (tx << 2);
                const float* pe = d_pe + (size_t)n * HIDDEN + j0;
                float4 o;
                o.x = acc[ih * 4 + i][jh * 4 + 0] + pb[j0 + 0] + pe[0];
                o.y = acc[ih * 4 + i][jh * 4 + 1] + pb[j0 + 1] + pe[1];
                o.z = acc[ih * 4 + i][jh * 4 + 2] + pb[j0 + 2] + pe[2];
                o.w = acc[ih * 4 + i][jh * 4 + 3] + pb[j0 + 3] + pe[3];
                *(float4*)&d_tokens[((size_t)b * NTOK + n) * HIDDEN + j0] = o;
            }
        }
}

// ---------------- flash attention: per (b,h), 64-row q-tile --------------------
__global__ void attn_kernel(const float* __restrict__ lam_p) {
    extern __shared__ float sm[];
    float* Qt  = sm;              // [64 k][68] : Qt[k][r]
    float* Kt  = Qt + 64 * 68;    // [64 k][68] : Kt[k][c]
    float* Vs  = Kt + 64 * 68;    // [64 c][68] : Vs[c][d]
    float* St  = Vs + 64 * 68;    // [64 c][68] : St[c][r]  (scores transposed)
    float* msh = St + 64 * 68;
    float* lsh = msh + 64;
    float* ash = lsh + 64;
    float* gq  = ash + 64;
    float* gk  = gq + 64;

    int tid = threadIdx.x;
    int tx = tid & 15, ty = tid >> 4;
    int n0 = blockIdx.x * 64;
    int h  = blockIdx.y;
    int b  = blockIdx.z;
    const float lam = *lam_p;
    size_t base = (size_t)(b * NHEAD + h) * NTOK * HD;

    for (int idx = tid; idx < 64 * 64; idx += 256) {
        int r = idx >> 6, k = idx & 63;
        Qt[k * 68 + r] = d_q[base + (size_t)(n0 + r) * HD + k];
    }
    if (tid < 64) {
        msh[tid] = -CUDART_INF_F;
        lsh[tid] = 0.0f;
        gq[tid]  = d_g[b * NTOK + n0 + tid];
    }

    const int sr   = tid >> 2;   // softmax: row per 4-thread group
    const int part = tid & 3;    // 16 cols each

    float o[4][4] = {};
    for (int k0 = 0; k0 < NTOK; k0 += 64) {
        __syncthreads();
        for (int idx = tid; idx < 64 * 64; idx += 256) {
            int c = idx >> 6, k = idx & 63;
            Kt[k * 68 + c] = d_k[base + (size_t)(k0 + c) * HD + k];
            Vs[c * 68 + k] = d_v[base + (size_t)(k0 + c) * HD + k];
        }
        if (tid < 64) gk[tid] = d_g[b * NTOK + k0 + tid];
        __syncthreads();

        // GEMM1: s = Q K^T
        float s[4][4] = {};
        #pragma unroll
        for (int kk = 0; kk < 64; kk++) {
            float4 qv = *(const float4*)(Qt + kk * 68 + ty * 4);
            float4 kv = *(const float4*)(Kt + kk * 68 + tx * 4);
            float a[4] = {qv.x, qv.y, qv.z, qv.w};
            float bb[4] = {kv.x, kv.y, kv.z, kv.w};
            #pragma unroll
            for (int i = 0; i < 4; i++)
                #pragma unroll
                for (int j = 0; j < 4; j++)
                    s[i][j] += a[i] * bb[j];
        }
        // scale + gaussian bias; store transposed
        #pragma unroll
        for (int i = 0; i < 4; i++) {
            float gqi = gq[ty * 4 + i];
            #pragma unroll
            for (int j = 0; j < 4; j++) {
                float v = s[i][j] * 0.125f + lam * gqi * gk[tx * 4 + j];
                St[(tx * 4 + j) * 68 + ty * 4 + i] = v;
            }
        }
        __syncthreads();

        // online softmax: 4 threads per row, butterfly reduce
        {
            float m_old = msh[sr];
            float mx = m_old;
            #pragma unroll
            for (int cc = 0; cc < 16; cc++)
                mx = fmaxf(mx, St[(part * 16 + cc) * 68 + sr]);
            mx = fmaxf(mx, __shfl_xor_sync(0xffffffffu, mx, 1));
            mx = fmaxf(mx, __shfl_xor_sync(0xffffffffu, mx, 2));
            float sum = 0.0f;
            #pragma unroll
            for (int cc = 0; cc < 16; cc++) {
                int idx = (part * 16 + cc) * 68 + sr;
                float p = __expf(St[idx] - mx);
                St[idx] = p;
                sum += p;
            }
            sum += __shfl_xor_sync(0xffffffffu, sum, 1);
            sum += __shfl_xor_sync(0xffffffffu, sum, 2);
            if (part == 0) {
                float alpha = __expf(m_old - mx);
                msh[sr] = mx;
                lsh[sr] = lsh[sr] * alpha + sum;
                ash[sr] = alpha;
            }
        }
        __syncthreads();

        float al[4];
        #pragma unroll
        for (int i = 0; i < 4; i++) al[i] = ash[ty * 4 + i];
        #pragma unroll
        for (int i = 0; i < 4; i++)
            #pragma unroll
            for (int j = 0; j < 4; j++)
                o[i][j] *= al[i];

        // GEMM2: o += P V
        #pragma unroll
        for (int c = 0; c < 64; c++) {
            float4 pv = *(const float4*)(St + c * 68 + ty * 4);
            float4 vv = *(const float4*)(Vs + c * 68 + tx * 4);
            float p[4] = {pv.x, pv.y, pv.z, pv.w};
            float vvv[4] = {vv.x, vv.y, vv.z, vv.w};
            #pragma unroll
            for (int i = 0; i < 4; i++)
                #pragma unroll
                for (int j = 0; j < 4; j++)
                    o[i][j] += p[i] * vvv[j];
        }
    }

    float linv[4];
    #pragma unroll
    for (int i = 0; i < 4; i++) linv[i] = 1.0f / lsh[ty * 4 + i];
    #pragma unroll
    for (int i = 0; i < 4; i++) {
        int n = n0 + ty * 4 + i;
        float4 ov;
        ov.x = o[i][0] * linv[i];
        ov.y = o[i][1] * linv[i];
        ov.z = o[i][2] * linv[i];
        ov.w = o[i][3] * linv[i];
        *(float4*)&d_attn[((size_t)b * NTOK + n) * HIDDEN + h * HD + tx * 4] = ov;
    }
}

// ---------------- launch --------------------------------------------------------
extern "C" void kernel_launch(void* const* d_in, const int* in_sizes, int n_in,
                              void* d_out, int out_size) {
    const float* feat = (const float*)d_in[0];
    const float* I    = (const float*)d_in[1];
    const float* pw   = (const float*)d_in[2];
    const float* pb   = (const float*)d_in[3];
    const float* wq   = (const float*)d_in[4];
    const float* bq   = (const float*)d_in[5];
    const float* wk   = (const float*)d_in[6];
    const float* bk   = (const float*)d_in[7];
    const float* wv   = (const float*)d_in[8];
    const float* bv   = (const float*)d_in[9];
    const float* wo   = (const float*)d_in[10];
    const float* bo   = (const float*)d_in[11];
    const float* lam  = (const float*)d_in[12];
    float* out = (float*)d_out;

    float *tok, *q, *k, *v, *attn;
    cudaGetSymbolAddress((void**)&tok,  d_tokens);
    cudaGetSymbolAddress((void**)&q,    d_q);
    cudaGetSymbolAddress((void**)&k,    d_k);
    cudaGetSymbolAddress((void**)&v,    d_v);
    cudaGetSymbolAddress((void**)&attn, d_attn);

    pe_kernel<<<(NTOK * HIDDEN + 255) / 256, 256>>>();
    gauss_kernel<<<(M_TOT + 255) / 256, 256>>>(I);

    // projection (feat^T @ pw + pb + pe)
    proj128_kernel<<<dim3(HIDDEN / 128, NTOK / 128, BATCH), 256>>>(feat, pw, pb);

    // QKV GEMMs (write [b,h,n,d])
    dim3 gBig(HIDDEN / 128, M_TOT / 128);
    gemm128_kernel<1><<<gBig, 256>>>(tok, wq, bq, q);
    gemm128_kernel<1><<<gBig, 256>>>(tok, wk, bk, k);
    gemm128_kernel<1><<<gBig, 256>>>(tok, wv, bv, v);

    // attention
    size_t smem = (4 * 64 * 68 + 5 * 64) * sizeof(float);  // 70912 B
    cudaFuncSetAttribute(attn_kernel, cudaFuncAttributeMaxDynamicSharedMemorySize,
                         (int)smem);
    attn_kernel<<<dim3(NTOK / 64, NHEAD, BATCH), 256, smem>>>(lam);

    // output projection
    gemm128_kernel<0><<<gBig, 256>>>(attn, wo, bo, out);
}

// round 9
// speedup vs baseline: 1.3542x; 1.1560x over previous
#include <cuda_runtime.h>
#include <cuda_bf16.h>
#include <math.h>
#include <math_constants.h>

#define HIDDEN 768
#define NHEAD  12
#define HD     64
#define BATCH  8
#define NTOK   1024
#define C_IN   256
#define M_TOT  (BATCH * NTOK)
#define KW     384            // HIDDEN/2 words (bf16x2 along k)

// ---------------- scratch (static device arrays; no allocation) ----------------
__device__ float d_q[M_TOT * HIDDEN];
__device__ float d_k[M_TOT * HIDDEN];
__device__ float d_v[M_TOT * HIDDEN];
__device__ float d_g[M_TOT];
__device__ float d_pe[NTOK * HIDDEN];
// bf16 hi/lo split activations (packed bf16x2 words, k-contiguous)
__device__ unsigned d_tokh[M_TOT * KW];
__device__ unsigned d_tokl[M_TOT * KW];
__device__ unsigned d_ath[M_TOT * KW];
__device__ unsigned d_atl[M_TOT * KW];
// transposed + split weights: [n][k] as bf16x2 words [768][384]
__device__ unsigned d_wqh[HIDDEN * KW];
__device__ unsigned d_wql[HIDDEN * KW];
__device__ unsigned d_wkh[HIDDEN * KW];
__device__ unsigned d_wkl[HIDDEN * KW];
__device__ unsigned d_wvh[HIDDEN * KW];
__device__ unsigned d_wvl[HIDDEN * KW];
__device__ unsigned d_woh[HIDDEN * KW];
__device__ unsigned d_wol[HIDDEN * KW];

// ---------------- helpers --------------------------------------------------------
__device__ __forceinline__ void splitpack(float x0, float x1, unsigned& h, unsigned& l) {
    __nv_bfloat16 h0 = __float2bfloat16_rn(x0), h1 = __float2bfloat16_rn(x1);
    float r0 = x0 - __bfloat162float(h0), r1 = x1 - __bfloat162float(h1);
    __nv_bfloat16 l0 = __float2bfloat16_rn(r0), l1 = __float2bfloat16_rn(r1);
    h = ((unsigned)__bfloat16_as_ushort(h1) << 16) | (unsigned)__bfloat16_as_ushort(h0);
    l = ((unsigned)__bfloat16_as_ushort(l1) << 16) | (unsigned)__bfloat16_as_ushort(l0);
}

// m16n8k16 bf16 MMA, fp32 accumulate in place
__device__ __forceinline__ void mma16(float* c, unsigned a0, unsigned a1,
                                      unsigned a2, unsigned a3,
                                      unsigned b0, unsigned b1) {
    asm volatile(
        "mma.sync.aligned.m16n8k16.row.col.f32.bf16.bf16.f32 "
        "{%0,%1,%2,%3}, {%4,%5,%6,%7}, {%8,%9}, {%0,%1,%2,%3};"
        : "+f"(c[0]), "+f"(c[1]), "+f"(c[2]), "+f"(c[3])
        : "r"(a0), "r"(a1), "r"(a2), "r"(a3), "r"(b0), "r"(b1));
}

// ---------------- positional encoding -------------------------------------------
__global__ void pe_kernel() {
    int idx = blockIdx.x * blockDim.x + threadIdx.x;
    if (idx >= NTOK * HIDDEN) return;
    int n = idx / HIDDEN, d = idx % HIDDEN;
    int i2 = d & ~1;
    float div = expf((float)i2 * -0.011992630692677323f);  // -ln(10000)/768
    float ph = (float)n * div;
    d_pe[idx] = (d & 1) ? cosf(ph) : sinf(ph);
}

// ---------------- gaussian weights -----------------------------------------------
__global__ void gauss_kernel(const float* __restrict__ I) {
    int idx = blockIdx.x * blockDim.x + threadIdx.x;
    if (idx >= M_TOT) return;
    float x = I[idx];
    float x2 = x * x;
    const float d0 = 2.0f * 0.25f + 1e-5f;
    const float d1 = 2.0f * 1.00f + 1e-5f;
    const float d2 = 2.0f * 4.00f + 1e-5f;
    float g = (expf(-x2 / d0) + expf(-x2 / d1) + expf(-x2 / d2)) * (1.0f / 3.0f);
    d_g[idx] = g;
}

// ---------------- weight transpose + split: W[k][n] fp32 -> Th/Tl[n][k] bf16 ------
__global__ void wsplit_kernel(const float* __restrict__ W,
                              unsigned short* __restrict__ Th,
                              unsigned short* __restrict__ Tl) {
    __shared__ float tile[32][33];
    int tx = threadIdx.x, ty = threadIdx.y;      // 32 x 8
    int n0 = blockIdx.x * 32, k0 = blockIdx.y * 32;
    #pragma unroll
    for (int r = 0; r < 32; r += 8)
        tile[ty + r][tx] = W[(size_t)(k0 + ty + r) * HIDDEN + n0 + tx];
    __syncthreads();
    #pragma unroll
    for (int r = 0; r < 32; r += 8) {
        float x = tile[tx][ty + r];              // k = k0+tx, n = n0+ty+r
        __nv_bfloat16 h = __float2bfloat16_rn(x);
        float res = x - __bfloat162float(h);
        __nv_bfloat16 l = __float2bfloat16_rn(res);
        size_t o = (size_t)(n0 + ty + r) * HIDDEN + k0 + tx;
        Th[o] = __bfloat16_as_ushort(h);
        Tl[o] = __bfloat16_as_ushort(l);
    }
}

// ================= bf16-split tensor-core GEMM =====================================
// C[M,768] = (Ah+Al)[M,768] @ (Bh+Bl)^T + bias, operands pre-split bf16.
// Bh/Bl are [n][k] (transposed). 128x128 block, BK=16, 8 warps (2x4).
// QKV==1: write [b,h,n,hd] fp32; else row-major fp32.
template <int QKV>
__global__ __launch_bounds__(256, 2)
void gemm_bf16(const unsigned* __restrict__ Ah, const unsigned* __restrict__ Al,
               const unsigned* __restrict__ Bh, const unsigned* __restrict__ Bl,
               const float* __restrict__ bias, float* __restrict__ Cout) {
    __shared__ unsigned Ahs[2][128][9], Als[2][128][9];
    __shared__ unsigned Bhs[2][128][9], Bls[2][128][9];
    const int tid = threadIdx.x;
    const int lane = tid & 31, wid = tid >> 5;
    const int wm = wid & 1, wn = wid >> 1;          // 2 x 4 warp grid
    const int g = lane >> 2, tg = lane & 3;
    const int n0 = blockIdx.x * 128, m0 = blockIdx.y * 128;

    const int lr = tid >> 1;                 // 0..127 (tile row)
    const int lh = (tid & 1) * 4;            // word offset 0 or 4

    const unsigned* ApH = Ah + (size_t)(m0 + lr) * KW + lh;
    const unsigned* ApL = Al + (size_t)(m0 + lr) * KW + lh;
    const unsigned* BpH = Bh + (size_t)(n0 + lr) * KW + lh;
    const unsigned* BpL = Bl + (size_t)(n0 + lr) * KW + lh;

    uint4 rah = *(const uint4*)ApH, ral = *(const uint4*)ApL;
    uint4 rbh = *(const uint4*)BpH, rbl = *(const uint4*)BpL;

    float acc[4][4][4];
    #pragma unroll
    for (int i = 0; i < 4; i++)
        #pragma unroll
        for (int j = 0; j < 4; j++)
            #pragma unroll
            for (int r = 0; r < 4; r++) acc[i][j][r] = 0.0f;

    // store tile 0 (scalar stores; ld=9 keeps fragment reads conflict-free)
    Ahs[0][lr][lh+0]=rah.x; Ahs[0][lr][lh+1]=rah.y; Ahs[0][lr][lh+2]=rah.z; Ahs[0][lr][lh+3]=rah.w;
    Als[0][lr][lh+0]=ral.x; Als[0][lr][lh+1]=ral.y; Als[0][lr][lh+2]=ral.z; Als[0][lr][lh+3]=ral.w;
    Bhs[0][lr][lh+0]=rbh.x; Bhs[0][lr][lh+1]=rbh.y; Bhs[0][lr][lh+2]=rbh.z; Bhs[0][lr][lh+3]=rbh.w;
    Bls[0][lr][lh+0]=rbl.x; Bls[0][lr][lh+1]=rbl.y; Bls[0][lr][lh+2]=rbl.z; Bls[0][lr][lh+3]=rbl.w;

    int buf = 0;
    #pragma unroll 1
    for (int t = 0; t < 48; t++) {           // K = 768 = 48 slabs of 16
        if (t < 47) {
            rah = *(const uint4*)(ApH + (t + 1) * 8);
            ral = *(const uint4*)(ApL + (t + 1) * 8);
            rbh = *(const uint4*)(BpH + (t + 1) * 8);
            rbl = *(const uint4*)(BpL + (t + 1) * 8);
        }
        __syncthreads();

        // B fragments for all nf (kept in regs)
        unsigned bh0[4], bh1[4], bl0[4], bl1[4];
        #pragma unroll
        for (int nf = 0; nf < 4; nf++) {
            int cn = wn * 32 + nf * 8 + g;
            bh0[nf] = Bhs[buf][cn][tg];   bh1[nf] = Bhs[buf][cn][tg + 4];
            bl0[nf] = Bls[buf][cn][tg];   bl1[nf] = Bls[buf][cn][tg + 4];
        }
        #pragma unroll
        for (int mf = 0; mf < 4; mf++) {
            int rm = wm * 64 + mf * 16 + g;
            unsigned ah0 = Ahs[buf][rm][tg],     ah1 = Ahs[buf][rm + 8][tg];
            unsigned ah2 = Ahs[buf][rm][tg + 4], ah3 = Ahs[buf][rm + 8][tg + 4];
            unsigned al0 = Als[buf][rm][tg],     al1 = Als[buf][rm + 8][tg];
            unsigned al2 = Als[buf][rm][tg + 4], al3 = Als[buf][rm + 8][tg + 4];
            #pragma unroll
            for (int nf = 0; nf < 4; nf++) {
                mma16(acc[mf][nf], ah0, ah1, ah2, ah3, bh0[nf], bh1[nf]); // hi*hi
                mma16(acc[mf][nf], ah0, ah1, ah2, ah3, bl0[nf], bl1[nf]); // hi*lo
                mma16(acc[mf][nf], al0, al1, al2, al3, bh0[nf], bh1[nf]); // lo*hi
            }
        }
        if (t < 47) {
            int nb = buf ^ 1;
            Ahs[nb][lr][lh+0]=rah.x; Ahs[nb][lr][lh+1]=rah.y; Ahs[nb][lr][lh+2]=rah.z; Ahs[nb][lr][lh+3]=rah.w;
            Als[nb][lr][lh+0]=ral.x; Als[nb][lr][lh+1]=ral.y; Als[nb][lr][lh+2]=ral.z; Als[nb][lr][lh+3]=ral.w;
            Bhs[nb][lr][lh+0]=rbh.x; Bhs[nb][lr][lh+1]=rbh.y; Bhs[nb][lr][lh+2]=rbh.z; Bhs[nb][lr][lh+3]=rbh.w;
            Bls[nb][lr][lh+0]=rbl.x; Bls[nb][lr][lh+1]=rbl.y; Bls[nb][lr][lh+2]=rbl.z; Bls[nb][lr][lh+3]=rbl.w;
        }
        buf ^= 1;
    }

    // epilogue: C fragment (g,2tg),(g,2tg+1),(g+8,2tg),(g+8,2tg+1)
    #pragma unroll
    for (int mf = 0; mf < 4; mf++) {
        int r0 = m0 + wm * 64 + mf * 16 + g;
        #pragma unroll
        for (int nf = 0; nf < 4; nf++) {
            int j = n0 + wn * 32 + nf * 8 + 2 * tg;
            float2 v0, v1;
            v0.x = acc[mf][nf][0] + bias[j];
            v0.y = acc[mf][nf][1] + bias[j + 1];
            v1.x = acc[mf][nf][2] + bias[j];
            v1.y = acc[mf][nf][3] + bias[j + 1];
            if (QKV) {
                int h = j >> 6, dd = j & 63;
                int b0i = r0 >> 10, nn0 = r0 & 1023;
                *(float2*)&Cout[(((size_t)(b0i * NHEAD + h) * NTOK) + nn0) * HD + dd] = v0;
                int r1 = r0 + 8;
                int b1i = r1 >> 10, nn1 = r1 & 1023;
                *(float2*)&Cout[(((size_t)(b1i * NHEAD + h) * NTOK) + nn1) * HD + dd] = v1;
            } else {
                *(float2*)&Cout[(size_t)r0 * HIDDEN + j] = v0;
                *(float2*)&Cout[(size_t)(r0 + 8) * HIDDEN + j] = v1;
            }
        }
    }
}

// ================= projection (proven fp32 compute, split epilogue) ==============
// tokens = feat^T @ pw + pb + pe  -> written as bf16 hi/lo words
__global__ __launch_bounds__(256, 2)
void proj128_kernel(const float* __restrict__ feat, const float* __restrict__ pw,
                    const float* __restrict__ pb) {
    __shared__ float As[2][16][128];
    __shared__ float Bs[2][16][128];
    const int tid = threadIdx.x;
    const int tx = tid & 15, ty = tid >> 4;
    const int d0 = blockIdx.x * 128;
    const int n0 = blockIdx.y * 128;
    const int b  = blockIdx.z;
    const float* fb = feat + (size_t)b * C_IN * NTOK;

    const int akr = tid >> 5;
    const int am4 = (tid & 31) << 2;

    const float* Fp0 = fb + (size_t)akr * NTOK + n0 + am4;
    const float* Fp1 = Fp0 + (size_t)8 * NTOK;
    const float* Wp0 = pw + (size_t)akr * HIDDEN + d0 + am4;
    const float* Wp1 = Wp0 + (size_t)8 * HIDDEN;

    float4 a0 = *(const float4*)Fp0;
    float4 a1 = *(const float4*)Fp1;
    float4 b0 = *(const float4*)Wp0;
    float4 b1 = *(const float4*)Wp1;

    float acc[8][8];
    #pragma unroll
    for (int i = 0; i < 8; i++)
        #pragma unroll
        for (int j = 0; j < 8; j++) acc[i][j] = 0.0f;

    *(float4*)&As[0][akr][am4] = a0;
    *(float4*)&As[0][akr + 8][am4] = a1;
    *(float4*)&Bs[0][akr][am4] = b0;
    *(float4*)&Bs[0][akr + 8][am4] = b1;

    int buf = 0;
    #pragma unroll 1
    for (int t = 0; t < 16; t++) {
        if (t < 15) {
            a0 = *(const float4*)(Fp0 + (size_t)(t + 1) * 16 * NTOK);
            a1 = *(const float4*)(Fp1 + (size_t)(t + 1) * 16 * NTOK);
            b0 = *(const float4*)(Wp0 + (size_t)(t + 1) * 16 * HIDDEN);
            b1 = *(const float4*)(Wp1 + (size_t)(t + 1) * 16 * HIDDEN);
        }
        __syncthreads();
        #pragma unroll
        for (int kk = 0; kk < 16; kk++) {
            float4 x0 = *(const float4*)&As[buf][kk][ty << 2];
            float4 x1 = *(const float4*)&As[buf][kk][64 + (ty << 2)];
            float4 y0 = *(const float4*)&Bs[buf][kk][tx << 2];
            float4 y1 = *(const float4*)&Bs[buf][kk][64 + (tx << 2)];
            float xa[8] = {x0.x, x0.y, x0.z, x0.w, x1.x, x1.y, x1.z, x1.w};
            float yb[8] = {y0.x, y0.y, y0.z, y0.w, y1.x, y1.y, y1.z, y1.w};
            #pragma unroll
            for (int i = 0; i < 8; i++)
                #pragma unroll
                for (int j = 0; j < 8; j++)
                    acc[i][j] += xa[i] * yb[j];
        }
        if (t < 15) {
            int nb = buf ^ 1;
            *(float4*)&As[nb][akr][am4] = a0;
            *(float4*)&As[nb][akr + 8][am4] = a1;
            *(float4*)&Bs[nb][akr][am4] = b0;
            *(float4*)&Bs[nb][akr + 8][am4] = b1;
        }
        buf ^= 1;
    }

    #pragma unroll
    for (int ih = 0; ih < 2; ih++)
        #pragma unroll
        for (int i = 0; i < 4; i++) {
            int n = n0 + ih * 64 + (ty << 2) + i;
            #pragma unroll
            for (int jh = 0; jh < 2; jh++) {
                int j0 = d0 + jh * 64 + (tx << 2);
                const float* pe = d_pe + (size_t)n * HIDDEN + j0;
                float o0 = acc[ih * 4 + i][jh * 4 + 0] + pb[j0 + 0] + pe[0];
                float o1 = acc[ih * 4 + i][jh * 4 + 1] + pb[j0 + 1] + pe[1];
                float o2 = acc[ih * 4 + i][jh * 4 + 2] + pb[j0 + 2] + pe[2];
                float o3 = acc[ih * 4 + i][jh * 4 + 3] + pb[j0 + 3] + pe[3];
                unsigned hw0, lw0, hw1, lw1;
                splitpack(o0, o1, hw0, lw0);
                splitpack(o2, o3, hw1, lw1);
                size_t wb = ((size_t)b * NTOK + n) * KW + (j0 >> 1);
                d_tokh[wb] = hw0; d_tokh[wb + 1] = hw1;
                d_tokl[wb] = lw0; d_tokl[wb + 1] = lw1;
            }
        }
}

// ---------------- flash attention (proven fp32 SIMT, split epilogue) -------------
__global__ void attn_kernel(const float* __restrict__ lam_p) {
    extern __shared__ float sm[];
    float* Qt  = sm;              // [64 k][68] : Qt[k][r]
    float* Kt  = Qt + 64 * 68;    // [64 k][68] : Kt[k][c]
    float* Vs  = Kt + 64 * 68;    // [64 c][68] : Vs[c][d]
    float* St  = Vs + 64 * 68;    // [64 c][68] : St[c][r]
    float* msh = St + 64 * 68;
    float* lsh = msh + 64;
    float* ash = lsh + 64;
    float* gq  = ash + 64;
    float* gk  = gq + 64;

    int tid = threadIdx.x;
    int tx = tid & 15, ty = tid >> 4;
    int n0 = blockIdx.x * 64;
    int h  = blockIdx.y;
    int b  = blockIdx.z;
    const float lam = *lam_p;
    size_t base = (size_t)(b * NHEAD + h) * NTOK * HD;

    for (int idx = tid; idx < 64 * 64; idx += 256) {
        int r = idx >> 6, k = idx & 63;
        Qt[k * 68 + r] = d_q[base + (size_t)(n0 + r) * HD + k];
    }
    if (tid < 64) {
        msh[tid] = -CUDART_INF_F;
        lsh[tid] = 0.0f;
        gq[tid]  = d_g[b * NTOK + n0 + tid];
    }

    const int sr   = tid >> 2;
    const int part = tid & 3;

    float o[4][4] = {};
    for (int k0 = 0; k0 < NTOK; k0 += 64) {
        __syncthreads();
        for (int idx = tid; idx < 64 * 64; idx += 256) {
            int c = idx >> 6, k = idx & 63;
            Kt[k * 68 + c] = d_k[base + (size_t)(k0 + c) * HD + k];
            Vs[c * 68 + k] = d_v[base + (size_t)(k0 + c) * HD + k];
        }
        if (tid < 64) gk[tid] = d_g[b * NTOK + k0 + tid];
        __syncthreads();

        float s[4][4] = {};
        #pragma unroll
        for (int kk = 0; kk < 64; kk++) {
            float4 qv = *(const float4*)(Qt + kk * 68 + ty * 4);
            float4 kv = *(const float4*)(Kt + kk * 68 + tx * 4);
            float a[4] = {qv.x, qv.y, qv.z, qv.w};
            float bb[4] = {kv.x, kv.y, kv.z, kv.w};
            #pragma unroll
            for (int i = 0; i < 4; i++)
                #pragma unroll
                for (int j = 0; j < 4; j++)
                    s[i][j] += a[i] * bb[j];
        }
        #pragma unroll
        for (int i = 0; i < 4; i++) {
            float gqi = gq[ty * 4 + i];
            #pragma unroll
            for (int j = 0; j < 4; j++) {
                float v = s[i][j] * 0.125f + lam * gqi * gk[tx * 4 + j];
                St[(tx * 4 + j) * 68 + ty * 4 + i] = v;
            }
        }
        __syncthreads();

        {
            float m_old = msh[sr];
            float mx = m_old;
            #pragma unroll
            for (int cc = 0; cc < 16; cc++)
                mx = fmaxf(mx, St[(part * 16 + cc) * 68 + sr]);
            mx = fmaxf(mx, __shfl_xor_sync(0xffffffffu, mx, 1));
            mx = fmaxf(mx, __shfl_xor_sync(0xffffffffu, mx, 2));
            float sum = 0.0f;
            #pragma unroll
            for (int cc = 0; cc < 16; cc++) {
                int idx = (part * 16 + cc) * 68 + sr;
                float p = __expf(St[idx] - mx);
                St[idx] = p;
                sum += p;
            }
            sum += __shfl_xor_sync(0xffffffffu, sum, 1);
            sum += __shfl_xor_sync(0xffffffffu, sum, 2);
            if (part == 0) {
                float alpha = __expf(m_old - mx);
                msh[sr] = mx;
                lsh[sr] = lsh[sr] * alpha + sum;
                ash[sr] = alpha;
            }
        }
        __syncthreads();

        float al[4];
        #pragma unroll
        for (int i = 0; i < 4; i++) al[i] = ash[ty * 4 + i];
        #pragma unroll
        for (int i = 0; i < 4; i++)
            #pragma unroll
            for (int j = 0; j < 4; j++)
                o[i][j] *= al[i];

        #pragma unroll
        for (int c = 0; c < 64; c++) {
            float4 pv = *(const float4*)(St + c * 68 + ty * 4);
            float4 vv = *(const float4*)(Vs + c * 68 + tx * 4);
            float p[4] = {pv.x, pv.y, pv.z, pv.w};
            float vvv[4] = {vv.x, vv.y, vv.z, vv.w};
            #pragma unroll
            for (int i = 0; i < 4; i++)
                #pragma unroll
                for (int j = 0; j < 4; j++)
                    o[i][j] += p[i] * vvv[j];
        }
    }

    float linv[4];
    #pragma unroll
    for (int i = 0; i < 4; i++) linv[i] = 1.0f / lsh[ty * 4 + i];
    #pragma unroll
    for (int i = 0; i < 4; i++) {
        int n = n0 + ty * 4 + i;
        float o0 = o[i][0] * linv[i];
        float o1 = o[i][1] * linv[i];
        float o2 = o[i][2] * linv[i];
        float o3 = o[i][3] * linv[i];
        unsigned hw0, lw0, hw1, lw1;
        splitpack(o0, o1, hw0, lw0);
        splitpack(o2, o3, hw1, lw1);
        size_t wb = ((size_t)b * NTOK + n) * KW + ((h * HD + tx * 4) >> 1);
        d_ath[wb] = hw0; d_ath[wb + 1] = hw1;
        d_atl[wb] = lw0; d_atl[wb + 1] = lw1;
    }
}

// ---------------- launch ----------------------------------------------------------
extern "C" void kernel_launch(void* const* d_in, const int* in_sizes, int n_in,
                              void* d_out, int out_size) {
    const float* feat = (const float*)d_in[0];
    const float* I    = (const float*)d_in[1];
    const float* pw   = (const float*)d_in[2];
    const float* pb   = (const float*)d_in[3];
    const float* wq   = (const float*)d_in[4];
    const float* bq   = (const float*)d_in[5];
    const float* wk   = (const float*)d_in[6];
    const float* bk   = (const float*)d_in[7];
    const float* wv   = (const float*)d_in[8];
    const float* bv   = (const float*)d_in[9];
    const float* wo   = (const float*)d_in[10];
    const float* bo   = (const float*)d_in[11];
    const float* lam  = (const float*)d_in[12];
    float* out = (float*)d_out;

    unsigned *tokh, *tokl, *ath, *atl;
    unsigned *wqh, *wql, *wkh, *wkl, *wvh, *wvl, *woh, *wol;
    float *q, *k, *v;
    cudaGetSymbolAddress((void**)&tokh, d_tokh);
    cudaGetSymbolAddress((void**)&tokl, d_tokl);
    cudaGetSymbolAddress((void**)&ath,  d_ath);
    cudaGetSymbolAddress((void**)&atl,  d_atl);
    cudaGetSymbolAddress((void**)&wqh,  d_wqh);
    cudaGetSymbolAddress((void**)&wql,  d_wql);
    cudaGetSymbolAddress((void**)&wkh,  d_wkh);
    cudaGetSymbolAddress((void**)&wkl,  d_wkl);
    cudaGetSymbolAddress((void**)&wvh,  d_wvh);
    cudaGetSymbolAddress((void**)&wvl,  d_wvl);
    cudaGetSymbolAddress((void**)&woh,  d_woh);
    cudaGetSymbolAddress((void**)&wol,  d_wol);
    cudaGetSymbolAddress((void**)&q,    d_q);
    cudaGetSymbolAddress((void**)&k,    d_k);
    cudaGetSymbolAddress((void**)&v,    d_v);

    pe_kernel<<<(NTOK * HIDDEN + 255) / 256, 256>>>();
    gauss_kernel<<<(M_TOT + 255) / 256, 256>>>(I);

    // weight transpose+split
    dim3 wsg(HIDDEN / 32, HIDDEN / 32);
    dim3 wsb(32, 8);
    wsplit_kernel<<<wsg, wsb>>>(wq, (unsigned short*)wqh, (unsigned short*)wql);
    wsplit_kernel<<<wsg, wsb>>>(wk, (unsigned short*)wkh, (unsigned short*)wkl);
    wsplit_kernel<<<wsg, wsb>>>(wv, (unsigned short*)wvh, (unsigned short*)wvl);
    wsplit_kernel<<<wsg, wsb>>>(wo, (unsigned short*)woh, (unsigned short*)wol);

    // projection (fp32 compute, writes tok hi/lo)
    proj128_kernel<<<dim3(HIDDEN / 128, NTOK / 128, BATCH), 256>>>(feat, pw, pb);

    // QKV GEMMs (bf16-split MMA; write fp32 [b,h,n,d])
    dim3 gBig(HIDDEN / 128, M_TOT / 128);
    gemm_bf16<1><<<gBig, 256>>>(tokh, tokl, wqh, wql, bq, q);
    gemm_bf16<1><<<gBig, 256>>>(tokh, tokl, wkh, wkl, bk, k);
    gemm_bf16<1><<<gBig, 256>>>(tokh, tokl, wvh, wvl, bv, v);

    // attention (fp32; writes attn hi/lo)
    size_t smem = (4 * 64 * 68 + 5 * 64) * sizeof(float);  // 70912 B
    cudaFuncSetAttribute(attn_kernel, cudaFuncAttributeMaxDynamicSharedMemorySize,
                         (int)smem);
    attn_kernel<<<dim3(NTOK / 64, NHEAD, BATCH), 256, smem>>>(lam);

    // output projection (bf16-split MMA)
    gemm_bf16<0><<<gBig, 256>>>(ath, atl, woh, wol, bo, out);
}

// round 10
// speedup vs baseline: 2.0283x; 1.4977x over previous
#include <cuda_runtime.h>
#include <cuda_bf16.h>
#include <math.h>
#include <math_constants.h>

#define HIDDEN 768
#define NHEAD  12
#define HD     64
#define BATCH  8
#define NTOK   1024
#define C_IN   256
#define M_TOT  (BATCH * NTOK)
#define KW     384            // HIDDEN/2 words (bf16x2 along k)
#define HW     32             // HD/2 words per head-row

// ---------------- scratch (static device arrays; no allocation) ----------------
__device__ float d_g[M_TOT];
__device__ float d_pe[NTOK * HIDDEN];
// bf16 hi/lo split activations (packed bf16x2 words, k-contiguous)
__device__ unsigned d_tokh[M_TOT * KW];
__device__ unsigned d_tokl[M_TOT * KW];
__device__ unsigned d_ath[M_TOT * KW];
__device__ unsigned d_atl[M_TOT * KW];
// split Q/K in [b,h,n,d-word] layout
__device__ unsigned d_qhw[M_TOT * HW * NHEAD / NHEAD * 1];  // placeholder sizing below
// (real definitions)
__device__ unsigned d_qh2[BATCH * NHEAD * NTOK * HW];
__device__ unsigned d_ql2[BATCH * NHEAD * NTOK * HW];
__device__ unsigned d_kh2[BATCH * NHEAD * NTOK * HW];
__device__ unsigned d_kl2[BATCH * NHEAD * NTOK * HW];
// split V^T in [b,h,d,n] ushort layout
__device__ unsigned short d_vth[BATCH * NHEAD * HD * NTOK];
__device__ unsigned short d_vtl[BATCH * NHEAD * HD * NTOK];
// transposed + split weights: [n][k] as bf16x2 words [768][384]
__device__ unsigned d_wqh[HIDDEN * KW];
__device__ unsigned d_wql[HIDDEN * KW];
__device__ unsigned d_wkh[HIDDEN * KW];
__device__ unsigned d_wkl[HIDDEN * KW];
__device__ unsigned d_wvh[HIDDEN * KW];
__device__ unsigned d_wvl[HIDDEN * KW];
__device__ unsigned d_woh[HIDDEN * KW];
__device__ unsigned d_wol[HIDDEN * KW];

// ---------------- helpers --------------------------------------------------------
__device__ __forceinline__ void splitpack(float x0, float x1, unsigned& h, unsigned& l) {
    __nv_bfloat16 h0 = __float2bfloat16_rn(x0), h1 = __float2bfloat16_rn(x1);
    float r0 = x0 - __bfloat162float(h0), r1 = x1 - __bfloat162float(h1);
    __nv_bfloat16 l0 = __float2bfloat16_rn(r0), l1 = __float2bfloat16_rn(r1);
    h = ((unsigned)__bfloat16_as_ushort(h1) << 16) | (unsigned)__bfloat16_as_ushort(h0);
    l = ((unsigned)__bfloat16_as_ushort(l1) << 16) | (unsigned)__bfloat16_as_ushort(l0);
}
__device__ __forceinline__ void split1(float x, unsigned short& h, unsigned short& l) {
    __nv_bfloat16 hb = __float2bfloat16_rn(x);
    __nv_bfloat16 lb = __float2bfloat16_rn(x - __bfloat162float(hb));
    h = __bfloat16_as_ushort(hb);
    l = __bfloat16_as_ushort(lb);
}

// m16n8k16 bf16 MMA, fp32 accumulate in place
__device__ __forceinline__ void mma16(float* c, unsigned a0, unsigned a1,
                                      unsigned a2, unsigned a3,
                                      unsigned b0, unsigned b1) {
    asm volatile(
        "mma.sync.aligned.m16n8k16.row.col.f32.bf16.bf16.f32 "
        "{%0,%1,%2,%3}, {%4,%5,%6,%7}, {%8,%9}, {%0,%1,%2,%3};"
        : "+f"(c[0]), "+f"(c[1]), "+f"(c[2]), "+f"(c[3])
        : "r"(a0), "r"(a1), "r"(a2), "r"(a3), "r"(b0), "r"(b1));
}

// ---------------- positional encoding -------------------------------------------
__global__ void pe_kernel() {
    int idx = blockIdx.x * blockDim.x + threadIdx.x;
    if (idx >= NTOK * HIDDEN) return;
    int n = idx / HIDDEN, d = idx % HIDDEN;
    int i2 = d & ~1;
    float div = expf((float)i2 * -0.011992630692677323f);  // -ln(10000)/768
    float ph = (float)n * div;
    d_pe[idx] = (d & 1) ? cosf(ph) : sinf(ph);
}

// ---------------- gaussian weights -----------------------------------------------
__global__ void gauss_kernel(const float* __restrict__ I) {
    int idx = blockIdx.x * blockDim.x + threadIdx.x;
    if (idx >= M_TOT) return;
    float x = I[idx];
    float x2 = x * x;
    const float d0 = 2.0f * 0.25f + 1e-5f;
    const float d1 = 2.0f * 1.00f + 1e-5f;
    const float d2 = 2.0f * 4.00f + 1e-5f;
    float g = (expf(-x2 / d0) + expf(-x2 / d1) + expf(-x2 / d2)) * (1.0f / 3.0f);
    d_g[idx] = g;
}

// ---------------- weight transpose + split: W[k][n] fp32 -> Th/Tl[n][k] bf16 ------
__global__ void wsplit_kernel(const float* __restrict__ W,
                              unsigned short* __restrict__ Th,
                              unsigned short* __restrict__ Tl) {
    __shared__ float tile[32][33];
    int tx = threadIdx.x, ty = threadIdx.y;      // 32 x 8
    int n0 = blockIdx.x * 32, k0 = blockIdx.y * 32;
    #pragma unroll
    for (int r = 0; r < 32; r += 8)
        tile[ty + r][tx] = W[(size_t)(k0 + ty + r) * HIDDEN + n0 + tx];
    __syncthreads();
    #pragma unroll
    for (int r = 0; r < 32; r += 8) {
        float x = tile[tx][ty + r];
        unsigned short hs, ls;
        split1(x, hs, ls);
        size_t o = (size_t)(n0 + ty + r) * HIDDEN + k0 + tx;
        Th[o] = hs;
        Tl[o] = ls;
    }
}

// ================= bf16-split tensor-core GEMM =====================================
// C[M,768] = (Ah+Al)[M,768] @ (Bh+Bl)^T + bias.
// MODE 0: fp32 row-major Cout. MODE 1: split words [b,h,n,d-word] (Ch,Cl unsigned*).
// MODE 2: split V^T ushort [b,h,d,n] (Vh,Vl ushort*).
template <int MODE>
__global__ __launch_bounds__(256, 2)
void gemm_bf16(const unsigned* __restrict__ Ah, const unsigned* __restrict__ Al,
               const unsigned* __restrict__ Bh, const unsigned* __restrict__ Bl,
               const float* __restrict__ bias, float* __restrict__ Cout,
               unsigned* __restrict__ Ch, unsigned* __restrict__ Cl,
               unsigned short* __restrict__ Vh, unsigned short* __restrict__ Vl) {
    __shared__ unsigned Ahs[2][128][9], Als[2][128][9];
    __shared__ unsigned Bhs[2][128][9], Bls[2][128][9];
    const int tid = threadIdx.x;
    const int lane = tid & 31, wid = tid >> 5;
    const int wm = wid & 1, wn = wid >> 1;          // 2 x 4 warp grid
    const int g = lane >> 2, tg = lane & 3;
    const int n0 = blockIdx.x * 128, m0 = blockIdx.y * 128;

    const int lr = tid >> 1;                 // 0..127 (tile row)
    const int lh = (tid & 1) * 4;            // word offset 0 or 4

    const unsigned* ApH = Ah + (size_t)(m0 + lr) * KW + lh;
    const unsigned* ApL = Al + (size_t)(m0 + lr) * KW + lh;
    const unsigned* BpH = Bh + (size_t)(n0 + lr) * KW + lh;
    const unsigned* BpL = Bl + (size_t)(n0 + lr) * KW + lh;

    uint4 rah = *(const uint4*)ApH, ral = *(const uint4*)ApL;
    uint4 rbh = *(const uint4*)BpH, rbl = *(const uint4*)BpL;

    float acc[4][4][4];
    #pragma unroll
    for (int i = 0; i < 4; i++)
        #pragma unroll
        for (int j = 0; j < 4; j++)
            #pragma unroll
            for (int r = 0; r < 4; r++) acc[i][j][r] = 0.0f;

    Ahs[0][lr][lh+0]=rah.x; Ahs[0][lr][lh+1]=rah.y; Ahs[0][lr][lh+2]=rah.z; Ahs[0][lr][lh+3]=rah.w;
    Als[0][lr][lh+0]=ral.x; Als[0][lr][lh+1]=ral.y; Als[0][lr][lh+2]=ral.z; Als[0][lr][lh+3]=ral.w;
    Bhs[0][lr][lh+0]=rbh.x; Bhs[0][lr][lh+1]=rbh.y; Bhs[0][lr][lh+2]=rbh.z; Bhs[0][lr][lh+3]=rbh.w;
    Bls[0][lr][lh+0]=rbl.x; Bls[0][lr][lh+1]=rbl.y; Bls[0][lr][lh+2]=rbl.z; Bls[0][lr][lh+3]=rbl.w;

    int buf = 0;
    #pragma unroll 1
    for (int t = 0; t < 48; t++) {           // K = 768 = 48 slabs of 16
        if (t < 47) {
            rah = *(const uint4*)(ApH + (t + 1) * 8);
            ral = *(const uint4*)(ApL + (t + 1) * 8);
            rbh = *(const uint4*)(BpH + (t + 1) * 8);
            rbl = *(const uint4*)(BpL + (t + 1) * 8);
        }
        __syncthreads();

        unsigned bh0[4], bh1[4], bl0[4], bl1[4];
        #pragma unroll
        for (int nf = 0; nf < 4; nf++) {
            int cn = wn * 32 + nf * 8 + g;
            bh0[nf] = Bhs[buf][cn][tg];   bh1[nf] = Bhs[buf][cn][tg + 4];
            bl0[nf] = Bls[buf][cn][tg];   bl1[nf] = Bls[buf][cn][tg + 4];
        }
        #pragma unroll
        for (int mf = 0; mf < 4; mf++) {
            int rm = wm * 64 + mf * 16 + g;
            unsigned ah0 = Ahs[buf][rm][tg],     ah1 = Ahs[buf][rm + 8][tg];
            unsigned ah2 = Ahs[buf][rm][tg + 4], ah3 = Ahs[buf][rm + 8][tg + 4];
            unsigned al0 = Als[buf][rm][tg],     al1 = Als[buf][rm + 8][tg];
            unsigned al2 = Als[buf][rm][tg + 4], al3 = Als[buf][rm + 8][tg + 4];
            #pragma unroll
            for (int nf = 0; nf < 4; nf++) {
                mma16(acc[mf][nf], ah0, ah1, ah2, ah3, bh0[nf], bh1[nf]);
                mma16(acc[mf][nf], ah0, ah1, ah2, ah3, bl0[nf], bl1[nf]);
                mma16(acc[mf][nf], al0, al1, al2, al3, bh0[nf], bh1[nf]);
            }
        }
        if (t < 47) {
            int nb = buf ^ 1;
            Ahs[nb][lr][lh+0]=rah.x; Ahs[nb][lr][lh+1]=rah.y; Ahs[nb][lr][lh+2]=rah.z; Ahs[nb][lr][lh+3]=rah.w;
            Als[nb][lr][lh+0]=ral.x; Als[nb][lr][lh+1]=ral.y; Als[nb][lr][lh+2]=ral.z; Als[nb][lr][lh+3]=ral.w;
            Bhs[nb][lr][lh+0]=rbh.x; Bhs[nb][lr][lh+1]=rbh.y; Bhs[nb][lr][lh+2]=rbh.z; Bhs[nb][lr][lh+3]=rbh.w;
            Bls[nb][lr][lh+0]=rbl.x; Bls[nb][lr][lh+1]=rbl.y; Bls[nb][lr][lh+2]=rbl.z; Bls[nb][lr][lh+3]=rbl.w;
        }
        buf ^= 1;
    }

    #pragma unroll
    for (int mf = 0; mf < 4; mf++) {
        int r0 = m0 + wm * 64 + mf * 16 + g;
        #pragma unroll
        for (int nf = 0; nf < 4; nf++) {
            int j = n0 + wn * 32 + nf * 8 + 2 * tg;
            float v00 = acc[mf][nf][0] + bias[j];
            float v01 = acc[mf][nf][1] + bias[j + 1];
            float v10 = acc[mf][nf][2] + bias[j];
            float v11 = acc[mf][nf][3] + bias[j + 1];
            int r1 = r0 + 8;
            if (MODE == 0) {
                *(float2*)&Cout[(size_t)r0 * HIDDEN + j] = make_float2(v00, v01);
                *(float2*)&Cout[(size_t)r1 * HIDDEN + j] = make_float2(v10, v11);
            } else if (MODE == 1) {
                int h = j >> 6, w = (j & 63) >> 1;
                int b0i = r0 >> 10, nn0 = r0 & 1023;
                int b1i = r1 >> 10, nn1 = r1 & 1023;
                unsigned hw, lw;
                size_t i0 = ((size_t)(b0i * NHEAD + h) * NTOK + nn0) * HW + w;
                splitpack(v00, v01, hw, lw); Ch[i0] = hw; Cl[i0] = lw;
                size_t i1 = ((size_t)(b1i * NHEAD + h) * NTOK + nn1) * HW + w;
                splitpack(v10, v11, hw, lw); Ch[i1] = hw; Cl[i1] = lw;
            } else {
                int h = j >> 6, dd = j & 63;
                int b0i = r0 >> 10, nn0 = r0 & 1023;
                int b1i = r1 >> 10, nn1 = r1 & 1023;
                unsigned short hs, ls;
                size_t base0 = ((size_t)(b0i * NHEAD + h) * HD + dd) * NTOK;
                size_t base1 = ((size_t)(b1i * NHEAD + h) * HD + dd) * NTOK;
                split1(v00, hs, ls); Vh[base0 + nn0]        = hs; Vl[base0 + nn0]        = ls;
                split1(v01, hs, ls); Vh[base0 + NTOK + nn0] = hs; Vl[base0 + NTOK + nn0] = ls;
                split1(v10, hs, ls); Vh[base1 + nn1]        = hs; Vl[base1 + nn1]        = ls;
                split1(v11, hs, ls); Vh[base1 + NTOK + nn1] = hs; Vl[base1 + NTOK + nn1] = ls;
            }
        }
    }
}

// ================= projection (fp32 compute, split epilogue) ======================
__global__ __launch_bounds__(256, 2)
void proj128_kernel(const float* __restrict__ feat, const float* __restrict__ pw,
                    const float* __restrict__ pb) {
    __shared__ float As[2][16][128];
    __shared__ float Bs[2][16][128];
    const int tid = threadIdx.x;
    const int tx = tid & 15, ty = tid >> 4;
    const int d0 = blockIdx.x * 128;
    const int n0 = blockIdx.y * 128;
    const int b  = blockIdx.z;
    const float* fb = feat + (size_t)b * C_IN * NTOK;

    const int akr = tid >> 5;
    const int am4 = (tid & 31) << 2;

    const float* Fp0 = fb + (size_t)akr * NTOK + n0 + am4;
    const float* Fp1 = Fp0 + (size_t)8 * NTOK;
    const float* Wp0 = pw + (size_t)akr * HIDDEN + d0 + am4;
    const float* Wp1 = Wp0 + (size_t)8 * HIDDEN;

    float4 a0 = *(const float4*)Fp0;
    float4 a1 = *(const float4*)Fp1;
    float4 b0 = *(const float4*)Wp0;
    float4 b1 = *(const float4*)Wp1;

    float acc[8][8];
    #pragma unroll
    for (int i = 0; i < 8; i++)
        #pragma unroll
        for (int j = 0; j < 8; j++) acc[i][j] = 0.0f;

    *(float4*)&As[0][akr][am4] = a0;
    *(float4*)&As[0][akr + 8][am4] = a1;
    *(float4*)&Bs[0][akr][am4] = b0;
    *(float4*)&Bs[0][akr + 8][am4] = b1;

    int buf = 0;
    #pragma unroll 1
    for (int t = 0; t < 16; t++) {
        if (t < 15) {
            a0 = *(const float4*)(Fp0 + (size_t)(t + 1) * 16 * NTOK);
            a1 = *(const float4*)(Fp1 + (size_t)(t + 1) * 16 * NTOK);
            b0 = *(const float4*)(Wp0 + (size_t)(t + 1) * 16 * HIDDEN);
            b1 = *(const float4*)(Wp1 + (size_t)(t + 1) * 16 * HIDDEN);
        }
        __syncthreads();
        #pragma unroll
        for (int kk = 0; kk < 16; kk++) {
            float4 x0 = *(const float4*)&As[buf][kk][ty << 2];
            float4 x1 = *(const float4*)&As[buf][kk][64 + (ty << 2)];
            float4 y0 = *(const float4*)&Bs[buf][kk][tx << 2];
            float4 y1 = *(const float4*)&Bs[buf][kk][64 + (tx << 2)];
            float xa[8] = {x0.x, x0.y, x0.z, x0.w, x1.x, x1.y, x1.z, x1.w};
            float yb[8] = {y0.x, y0.y, y0.z, y0.w, y1.x, y1.y, y1.z, y1.w};
            #pragma unroll
            for (int i = 0; i < 8; i++)
                #pragma unroll
                for (int j = 0; j < 8; j++)
                    acc[i][j] += xa[i] * yb[j];
        }
        if (t < 15) {
            int nb = buf ^ 1;
            *(float4*)&As[nb][akr][am4] = a0;
            *(float4*)&As[nb][akr + 8][am4] = a1;
            *(float4*)&Bs[nb][akr][am4] = b0;
            *(float4*)&Bs[nb][akr + 8][am4] = b1;
        }
        buf ^= 1;
    }

    #pragma unroll
    for (int ih = 0; ih < 2; ih++)
        #pragma unroll
        for (int i = 0; i < 4; i++) {
            int n = n0 + ih * 64 + (ty << 2) + i;
            #pragma unroll
            for (int jh = 0; jh < 2; jh++) {
                int j0 = d0 + jh * 64 + (tx << 2);
                const float* pe = d_pe + (size_t)n * HIDDEN + j0;
                float o0 = acc[ih * 4 + i][jh * 4 + 0] + pb[j0 + 0] + pe[0];
                float o1 = acc[ih * 4 + i][jh * 4 + 1] + pb[j0 + 1] + pe[1];
                float o2 = acc[ih * 4 + i][jh * 4 + 2] + pb[j0 + 2] + pe[2];
                float o3 = acc[ih * 4 + i][jh * 4 + 3] + pb[j0 + 3] + pe[3];
                unsigned hw0, lw0, hw1, lw1;
                splitpack(o0, o1, hw0, lw0);
                splitpack(o2, o3, hw1, lw1);
                size_t wb = ((size_t)b * NTOK + n) * KW + (j0 >> 1);
                d_tokh[wb] = hw0; d_tokh[wb + 1] = hw1;
                d_tokl[wb] = lw0; d_tokl[wb + 1] = lw1;
            }
        }
}

// ================= flash attention with bf16-split MMAs ==========================
// per (b,h), 64-row q-tile; 8 warps (4x2): wm = 16-row m-frag, wn = 32 of 64 d/c cols
__global__ __launch_bounds__(256)
void attn_mma(const float* __restrict__ lam_p) {
    extern __shared__ unsigned smw[];
    unsigned* Qh = smw;                  // [64][36]
    unsigned* Ql = Qh + 64 * 36;
    unsigned* Kh = Ql + 64 * 36;         // [c][d-word]
    unsigned* Kl = Kh + 64 * 36;
    unsigned* Vh = Kl + 64 * 36;         // V^T: [d][c-word]
    unsigned* Vl = Vh + 64 * 36;
    unsigned* Ph = Vl + 64 * 36;         // [r][c-word]
    unsigned* Pl = Ph + 64 * 36;
    float* St  = (float*)(Pl + 64 * 36); // [64][68] fp32 scores
    float* msh = St + 64 * 68;
    float* lsh = msh + 64;
    float* ash = lsh + 64;
    float* gq  = ash + 64;
    float* gk  = gq + 64;

    const int tid = threadIdx.x;
    const int lane = tid & 31, wid = tid >> 5;
    const int wm = wid & 3, wn = wid >> 2;
    const int g = lane >> 2, tg = lane & 3;
    const int n0 = blockIdx.x * 64;
    const int h = blockIdx.y, b = blockIdx.z;
    const float lam = *lam_p;
    const int rm = wm * 16 + g;

    const size_t qkbase = (size_t)(b * NHEAD + h) * NTOK * HW;
    const size_t vbase  = (size_t)(b * NHEAD + h) * HD * NTOK;   // ushort units

    const int lr = tid >> 2;           // 0..63
    const int wo = (tid & 3) * 8;      // word offset 0..24

    // load Q once
    {
        size_t o = qkbase + (size_t)(n0 + lr) * HW + wo;
        *(uint4*)&Qh[lr * 36 + wo]     = *(const uint4*)(d_qh2 + o);
        *(uint4*)&Qh[lr * 36 + wo + 4] = *(const uint4*)(d_qh2 + o + 4);
        *(uint4*)&Ql[lr * 36 + wo]     = *(const uint4*)(d_ql2 + o);
        *(uint4*)&Ql[lr * 36 + wo + 4] = *(const uint4*)(d_ql2 + o + 4);
    }
    if (tid < 64) {
        msh[tid] = -CUDART_INF_F;
        lsh[tid] = 0.0f;
        gq[tid]  = d_g[b * NTOK + n0 + tid];
    }

    const int sr = tid >> 2, part = tid & 3;

    float o[4][4];
    #pragma unroll
    for (int nf = 0; nf < 4; nf++)
        #pragma unroll
        for (int r = 0; r < 4; r++) o[nf][r] = 0.0f;

    for (int k0 = 0; k0 < NTOK; k0 += 64) {
        __syncthreads();
        {
            size_t ko = qkbase + (size_t)(k0 + lr) * HW + wo;
            *(uint4*)&Kh[lr * 36 + wo]     = *(const uint4*)(d_kh2 + ko);
            *(uint4*)&Kh[lr * 36 + wo + 4] = *(const uint4*)(d_kh2 + ko + 4);
            *(uint4*)&Kl[lr * 36 + wo]     = *(const uint4*)(d_kl2 + ko);
            *(uint4*)&Kl[lr * 36 + wo + 4] = *(const uint4*)(d_kl2 + ko + 4);
            // V^T rows: d = lr, c-words wo..wo+7 (= ushort idx k0 + 2*wo)
            size_t vo = vbase + (size_t)lr * NTOK + k0 + 2 * wo;
            *(uint4*)&Vh[lr * 36 + wo]     = *(const uint4*)(d_vth + vo);
            *(uint4*)&Vh[lr * 36 + wo + 4] = *(const uint4*)(d_vth + vo + 8);
            *(uint4*)&Vl[lr * 36 + wo]     = *(const uint4*)(d_vtl + vo);
            *(uint4*)&Vl[lr * 36 + wo + 4] = *(const uint4*)(d_vtl + vo + 8);
        }
        if (tid < 64) gk[tid] = d_g[b * NTOK + k0 + tid];
        __syncthreads();

        // S = Q K^T (hi/lo split, 3 MMAs per pair)
        float s[4][4];
        #pragma unroll
        for (int nf = 0; nf < 4; nf++)
            #pragma unroll
            for (int r = 0; r < 4; r++) s[nf][r] = 0.0f;
        #pragma unroll
        for (int s8 = 0; s8 < 4; s8++) {
            unsigned ah0 = Qh[rm * 36 + s8 * 8 + tg];
            unsigned ah1 = Qh[(rm + 8) * 36 + s8 * 8 + tg];
            unsigned ah2 = Qh[rm * 36 + s8 * 8 + 4 + tg];
            unsigned ah3 = Qh[(rm + 8) * 36 + s8 * 8 + 4 + tg];
            unsigned al0 = Ql[rm * 36 + s8 * 8 + tg];
            unsigned al1 = Ql[(rm + 8) * 36 + s8 * 8 + tg];
            unsigned al2 = Ql[rm * 36 + s8 * 8 + 4 + tg];
            unsigned al3 = Ql[(rm + 8) * 36 + s8 * 8 + 4 + tg];
            #pragma unroll
            for (int nf = 0; nf < 4; nf++) {
                int cn = wn * 32 + nf * 8 + g;
                unsigned bh0 = Kh[cn * 36 + s8 * 8 + tg];
                unsigned bh1 = Kh[cn * 36 + s8 * 8 + 4 + tg];
                unsigned bl0 = Kl[cn * 36 + s8 * 8 + tg];
                unsigned bl1 = Kl[cn * 36 + s8 * 8 + 4 + tg];
                mma16(s[nf], ah0, ah1, ah2, ah3, bh0, bh1);
                mma16(s[nf], ah0, ah1, ah2, ah3, bl0, bl1);
                mma16(s[nf], al0, al1, al2, al3, bh0, bh1);
            }
        }
        // scale + bias -> fp32 scores in St
        {
            float gq0 = gq[rm], gq1 = gq[rm + 8];
            #pragma unroll
            for (int nf = 0; nf < 4; nf++) {
                int c0 = wn * 32 + nf * 8 + 2 * tg;
                float gk0 = gk[c0], gk1 = gk[c0 + 1];
                St[rm * 68 + c0]           = s[nf][0] * 0.125f + lam * gq0 * gk0;
                St[rm * 68 + c0 + 1]       = s[nf][1] * 0.125f + lam * gq0 * gk1;
                St[(rm + 8) * 68 + c0]     = s[nf][2] * 0.125f + lam * gq1 * gk0;
                St[(rm + 8) * 68 + c0 + 1] = s[nf][3] * 0.125f + lam * gq1 * gk1;
            }
        }
        __syncthreads();

        // online softmax (4 threads/row) -> split P into Ph/Pl
        {
            float m_old = msh[sr];
            float mx = m_old;
            float pv[16];
            #pragma unroll
            for (int cc = 0; cc < 16; cc++) {
                pv[cc] = St[sr * 68 + part * 16 + cc];
                mx = fmaxf(mx, pv[cc]);
            }
            mx = fmaxf(mx, __shfl_xor_sync(0xffffffffu, mx, 1));
            mx = fmaxf(mx, __shfl_xor_sync(0xffffffffu, mx, 2));
            float sum = 0.0f;
            #pragma unroll
            for (int cc = 0; cc < 16; cc++) {
                pv[cc] = __expf(pv[cc] - mx);
                sum += pv[cc];
            }
            sum += __shfl_xor_sync(0xffffffffu, sum, 1);
            sum += __shfl_xor_sync(0xffffffffu, sum, 2);
            #pragma unroll
            for (int cc = 0; cc < 16; cc += 2) {
                unsigned hw, lw;
                splitpack(pv[cc], pv[cc + 1], hw, lw);
                Ph[sr * 36 + part * 8 + (cc >> 1)] = hw;
                Pl[sr * 36 + part * 8 + (cc >> 1)] = lw;
            }
            if (part == 0) {
                float alpha = __expf(m_old - mx);
                msh[sr] = mx;
                lsh[sr] = lsh[sr] * alpha + sum;
                ash[sr] = alpha;
            }
        }
        __syncthreads();

        // rescale accumulator, then O += P V
        {
            float al0 = ash[rm], al1 = ash[rm + 8];
            #pragma unroll
            for (int nf = 0; nf < 4; nf++) {
                o[nf][0] *= al0; o[nf][1] *= al0;
                o[nf][2] *= al1; o[nf][3] *= al1;
            }
        }
        #pragma unroll
        for (int s8 = 0; s8 < 4; s8++) {
            unsigned ah0 = Ph[rm * 36 + s8 * 8 + tg];
            unsigned ah1 = Ph[(rm + 8) * 36 + s8 * 8 + tg];
            unsigned ah2 = Ph[rm * 36 + s8 * 8 + 4 + tg];
            unsigned ah3 = Ph[(rm + 8) * 36 + s8 * 8 + 4 + tg];
            unsigned al0 = Pl[rm * 36 + s8 * 8 + tg];
            unsigned al1 = Pl[(rm + 8) * 36 + s8 * 8 + tg];
            unsigned al2 = Pl[rm * 36 + s8 * 8 + 4 + tg];
            unsigned al3 = Pl[(rm + 8) * 36 + s8 * 8 + 4 + tg];
            #pragma unroll
            for (int nf = 0; nf < 4; nf++) {
                int cn = wn * 32 + nf * 8 + g;          // d index
                unsigned bh0 = Vh[cn * 36 + s8 * 8 + tg];
                unsigned bh1 = Vh[cn * 36 + s8 * 8 + 4 + tg];
                unsigned bl0 = Vl[cn * 36 + s8 * 8 + tg];
                unsigned bl1 = Vl[cn * 36 + s8 * 8 + 4 + tg];
                mma16(o[nf], ah0, ah1, ah2, ah3, bh0, bh1);
                mma16(o[nf], ah0, ah1, ah2, ah3, bl0, bl1);
                mma16(o[nf], al0, al1, al2, al3, bh0, bh1);
            }
        }
    }

    // normalize, split, write to d_ath/d_atl
    {
        float li0 = 1.0f / lsh[rm], li1 = 1.0f / lsh[rm + 8];
        #pragma unroll
        for (int nf = 0; nf < 4; nf++) {
            int j = wn * 32 + nf * 8 + 2 * tg;          // d within head
            unsigned hw, lw;
            size_t w0 = ((size_t)b * NTOK + n0 + rm) * KW + ((h * HD + j) >> 1);
            splitpack(o[nf][0] * li0, o[nf][1] * li0, hw, lw);
            d_ath[w0] = hw; d_atl[w0] = lw;
            size_t w1 = ((size_t)b * NTOK + n0 + rm + 8) * KW + ((h * HD + j) >> 1);
            splitpack(o[nf][2] * li1, o[nf][3] * li1, hw, lw);
            d_ath[w1] = hw; d_atl[w1] = lw;
        }
    }
}

// ---------------- launch ----------------------------------------------------------
extern "C" void kernel_launch(void* const* d_in, const int* in_sizes, int n_in,
                              void* d_out, int out_size) {
    const float* feat = (const float*)d_in[0];
    const float* I    = (const float*)d_in[1];
    const float* pw   = (const float*)d_in[2];
    const float* pb   = (const float*)d_in[3];
    const float* wq   = (const float*)d_in[4];
    const float* bq   = (const float*)d_in[5];
    const float* wk   = (const float*)d_in[6];
    const float* bk   = (const float*)d_in[7];
    const float* wv   = (const float*)d_in[8];
    const float* bv   = (const float*)d_in[9];
    const float* wo   = (const float*)d_in[10];
    const float* bo   = (const float*)d_in[11];
    const float* lam  = (const float*)d_in[12];
    float* out = (float*)d_out;

    unsigned *tokh, *tokl, *ath, *atl;
    unsigned *wqh, *wql, *wkh, *wkl, *wvh, *wvl, *woh, *wol;
    unsigned *qh2, *ql2, *kh2, *kl2;
    unsigned short *vth, *vtl;
    cudaGetSymbolAddress((void**)&tokh, d_tokh);
    cudaGetSymbolAddress((void**)&tokl, d_tokl);
    cudaGetSymbolAddress((void**)&ath,  d_ath);
    cudaGetSymbolAddress((void**)&atl,  d_atl);
    cudaGetSymbolAddress((void**)&wqh,  d_wqh);
    cudaGetSymbolAddress((void**)&wql,  d_wql);
    cudaGetSymbolAddress((void**)&wkh,  d_wkh);
    cudaGetSymbolAddress((void**)&wkl,  d_wkl);
    cudaGetSymbolAddress((void**)&wvh,  d_wvh);
    cudaGetSymbolAddress((void**)&wvl,  d_wvl);
    cudaGetSymbolAddress((void**)&woh,  d_woh);
    cudaGetSymbolAddress((void**)&wol,  d_wol);
    cudaGetSymbolAddress((void**)&qh2,  d_qh2);
    cudaGetSymbolAddress((void**)&ql2,  d_ql2);
    cudaGetSymbolAddress((void**)&kh2,  d_kh2);
    cudaGetSymbolAddress((void**)&kl2,  d_kl2);
    cudaGetSymbolAddress((void**)&vth,  d_vth);
    cudaGetSymbolAddress((void**)&vtl,  d_vtl);

    pe_kernel<<<(NTOK * HIDDEN + 255) / 256, 256>>>();
    gauss_kernel<<<(M_TOT + 255) / 256, 256>>>(I);

    dim3 wsg(HIDDEN / 32, HIDDEN / 32);
    dim3 wsb(32, 8);
    wsplit_kernel<<<wsg, wsb>>>(wq, (unsigned short*)wqh, (unsigned short*)wql);
    wsplit_kernel<<<wsg, wsb>>>(wk, (unsigned short*)wkh, (unsigned short*)wkl);
    wsplit_kernel<<<wsg, wsb>>>(wv, (unsigned short*)wvh, (unsigned short*)wvl);
    wsplit_kernel<<<wsg, wsb>>>(wo, (unsigned short*)woh, (unsigned short*)wol);

    proj128_kernel<<<dim3(HIDDEN / 128, NTOK / 128, BATCH), 256>>>(feat, pw, pb);

    dim3 gBig(HIDDEN / 128, M_TOT / 128);
    gemm_bf16<1><<<gBig, 256>>>(tokh, tokl, wqh, wql, bq, nullptr, qh2, ql2, nullptr, nullptr);
    gemm_bf16<1><<<gBig, 256>>>(tokh, tokl, wkh, wkl, bk, nullptr, kh2, kl2, nullptr, nullptr);
    gemm_bf16<2><<<gBig, 256>>>(tokh, tokl, wvh, wvl, bv, nullptr, nullptr, nullptr, vth, vtl);

    size_t smem = (8 * 64 * 36) * 4 + (64 * 68 + 5 * 64) * 4;   // 92416 B
    cudaFuncSetAttribute(attn_mma, cudaFuncAttributeMaxDynamicSharedMemorySize,
                         (int)smem);
    attn_mma<<<dim3(NTOK / 64, NHEAD, BATCH), 256, smem>>>(lam);

    gemm_bf16<0><<<gBig, 256>>>(ath, atl, woh, wol, bo, out, nullptr, nullptr, nullptr, nullptr);
}

// round 13
// speedup vs baseline: 2.1263x; 1.0483x over previous
#include <cuda_runtime.h>
#include <cuda_bf16.h>
#include <math.h>
#include <math_constants.h>

#define HIDDEN 768
#define NHEAD  12
#define HD     64
#define BATCH  8
#define NTOK   1024
#define C_IN   256
#define M_TOT  (BATCH * NTOK)
#define KW     384            // HIDDEN/2 words (bf16x2 along k)
#define CW     128            // C_IN/2 words
#define HW     32             // HD/2 words per head-row

// ---------------- scratch (static device arrays; no allocation) ----------------
__device__ float d_g[M_TOT];
__device__ float d_pe[NTOK * HIDDEN];
// bf16 hi/lo split activations (packed bf16x2 words, k-contiguous)
__device__ unsigned d_tokh[M_TOT * KW];
__device__ unsigned d_tokl[M_TOT * KW];
__device__ unsigned d_ath[M_TOT * KW];
__device__ unsigned d_atl[M_TOT * KW];
// split feat^T: [m][c-word]
__device__ unsigned d_fth[M_TOT * CW];
__device__ unsigned d_ftl[M_TOT * CW];
// split Q/K in [b,h,n,d-word] layout
__device__ unsigned d_qh2[BATCH * NHEAD * NTOK * HW];
__device__ unsigned d_ql2[BATCH * NHEAD * NTOK * HW];
__device__ unsigned d_kh2[BATCH * NHEAD * NTOK * HW];
__device__ unsigned d_kl2[BATCH * NHEAD * NTOK * HW];
// split V^T in [b,h,d,n] ushort layout
__device__ unsigned short d_vth[BATCH * NHEAD * HD * NTOK];
__device__ unsigned short d_vtl[BATCH * NHEAD * HD * NTOK];
// transposed + split weights: [n][k]
__device__ unsigned d_pwh[HIDDEN * CW];
__device__ unsigned d_pwl[HIDDEN * CW];
__device__ unsigned d_wqh[HIDDEN * KW];
__device__ unsigned d_wql[HIDDEN * KW];
__device__ unsigned d_wkh[HIDDEN * KW];
__device__ unsigned d_wkl[HIDDEN * KW];
__device__ unsigned d_wvh[HIDDEN * KW];
__device__ unsigned d_wvl[HIDDEN * KW];
__device__ unsigned d_woh[HIDDEN * KW];
__device__ unsigned d_wol[HIDDEN * KW];

// ---------------- helpers --------------------------------------------------------
__device__ __forceinline__ void splitpack(float x0, float x1, unsigned& h, unsigned& l) {
    __nv_bfloat16 h0 = __float2bfloat16_rn(x0), h1 = __float2bfloat16_rn(x1);
    float r0 = x0 - __bfloat162float(h0), r1 = x1 - __bfloat162float(h1);
    __nv_bfloat16 l0 = __float2bfloat16_rn(r0), l1 = __float2bfloat16_rn(r1);
    h = ((unsigned)__bfloat16_as_ushort(h1) << 16) | (unsigned)__bfloat16_as_ushort(h0);
    l = ((unsigned)__bfloat16_as_ushort(l1) << 16) | (unsigned)__bfloat16_as_ushort(l0);
}
__device__ __forceinline__ void split1(float x, unsigned short& h, unsigned short& l) {
    __nv_bfloat16 hb = __float2bfloat16_rn(x);
    __nv_bfloat16 lb = __float2bfloat16_rn(x - __bfloat162float(hb));
    h = __bfloat16_as_ushort(hb);
    l = __bfloat16_as_ushort(lb);
}

// m16n8k16 bf16 MMA, fp32 accumulate in place
__device__ __forceinline__ void mma16(float* c, unsigned a0, unsigned a1,
                                      unsigned a2, unsigned a3,
                                      unsigned b0, unsigned b1) {
    asm volatile(
        "mma.sync.aligned.m16n8k16.row.col.f32.bf16.bf16.f32 "
        "{%0,%1,%2,%3}, {%4,%5,%6,%7}, {%8,%9}, {%0,%1,%2,%3};"
        : "+f"(c[0]), "+f"(c[1]), "+f"(c[2]), "+f"(c[3])
        : "r"(a0), "r"(a1), "r"(a2), "r"(a3), "r"(b0), "r"(b1));
}

// ---------------- positional encoding -------------------------------------------
__global__ void pe_kernel() {
    int idx = blockIdx.x * blockDim.x + threadIdx.x;
    if (idx >= NTOK * HIDDEN) return;
    int n = idx / HIDDEN, d = idx % HIDDEN;
    int i2 = d & ~1;
    float div = expf((float)i2 * -0.011992630692677323f);  // -ln(10000)/768
    float ph = (float)n * div;
    d_pe[idx] = (d & 1) ? cosf(ph) : sinf(ph);
}

// ---------------- gaussian weights -----------------------------------------------
__global__ void gauss_kernel(const float* __restrict__ I) {
    int idx = blockIdx.x * blockDim.x + threadIdx.x;
    if (idx >= M_TOT) return;
    float x = I[idx];
    float x2 = x * x;
    const float d0 = 2.0f * 0.25f + 1e-5f;
    const float d1 = 2.0f * 1.00f + 1e-5f;
    const float d2 = 2.0f * 4.00f + 1e-5f;
    float g = (expf(-x2 / d0) + expf(-x2 / d1) + expf(-x2 / d2)) * (1.0f / 3.0f);
    d_g[idx] = g;
}

// ------------- generic weight transpose + split: W[K][N] fp32 -> T[N][K] bf16 -----
__global__ void wsplitg_kernel(const float* __restrict__ W,
                               unsigned short* __restrict__ Th,
                               unsigned short* __restrict__ Tl,
                               int Kdim, int Ndim) {
    __shared__ float tile[32][33];
    int tx = threadIdx.x, ty = threadIdx.y;      // 32 x 8
    int n0 = blockIdx.x * 32, k0 = blockIdx.y * 32;
    #pragma unroll
    for (int r = 0; r < 32; r += 8)
        tile[ty + r][tx] = W[(size_t)(k0 + ty + r) * Ndim + n0 + tx];
    __syncthreads();
    #pragma unroll
    for (int r = 0; r < 32; r += 8) {
        float x = tile[tx][ty + r];              // k = k0+tx, n = n0+ty+r
        unsigned short hs, ls;
        split1(x, hs, ls);
        size_t o = (size_t)(n0 + ty + r) * Kdim + k0 + tx;
        Th[o] = hs;
        Tl[o] = ls;
    }
}

// ------------- feat transpose + split: feat[b,c,n] -> F[m=b*N+n][c] bf16 ----------
__global__ void fsplit_kernel(const float* __restrict__ feat,
                              unsigned short* __restrict__ Fh,
                              unsigned short* __restrict__ Fl) {
    __shared__ float tile[32][33];
    int tx = threadIdx.x, ty = threadIdx.y;      // 32 x 8
    int n0 = blockIdx.x * 32, c0 = blockIdx.y * 32, b = blockIdx.z;
    const float* fb = feat + (size_t)b * C_IN * NTOK;
    #pragma unroll
    for (int r = 0; r < 32; r += 8)
        tile[ty + r][tx] = fb[(size_t)(c0 + ty + r) * NTOK + n0 + tx];
    __syncthreads();
    #pragma unroll
    for (int r = 0; r < 32; r += 8) {
        float x = tile[tx][ty + r];              // c = c0+tx, n = n0+ty+r
        unsigned short hs, ls;
        split1(x, hs, ls);
        size_t o = ((size_t)b * NTOK + n0 + ty + r) * C_IN + c0 + tx;
        Fh[o] = hs;
        Fl[o] = ls;
    }
}

// ================= bf16-split tensor-core GEMM =====================================
// C[M,N=768] = (Ah+Al)[M,K] @ (Bh+Bl)^T + bias.  KWORDS = K/2.
// MODE 0: fp32 row-major Cout. MODE 1: split words [b,h,n,d-word].
// MODE 2: split V^T ushort [b,h,d,n]. MODE 3: tokens split (+bias+pe).
template <int MODE, int KWORDS>
__global__ __launch_bounds__(256, 2)
void gemm_bf16(const unsigned* __restrict__ Ah, const unsigned* __restrict__ Al,
               const unsigned* __restrict__ Bh, const unsigned* __restrict__ Bl,
               const float* __restrict__ bias, float* __restrict__ Cout,
               unsigned* __restrict__ Ch, unsigned* __restrict__ Cl,
               unsigned short* __restrict__ Vh, unsigned short* __restrict__ Vl) {
    __shared__ unsigned Ahs[2][128][9], Als[2][128][9];
    __shared__ unsigned Bhs[2][128][9], Bls[2][128][9];
    const int tid = threadIdx.x;
    const int lane = tid & 31, wid = tid >> 5;
    const int wm = wid & 1, wn = wid >> 1;          // 2 x 4 warp grid
    const int g = lane >> 2, tg = lane & 3;
    const int n0 = blockIdx.x * 128, m0 = blockIdx.y * 128;

    const int lr = tid >> 1;                 // 0..127 (tile row)
    const int lh = (tid & 1) * 4;            // word offset 0 or 4

    const unsigned* ApH = Ah + (size_t)(m0 + lr) * KWORDS + lh;
    const unsigned* ApL = Al + (size_t)(m0 + lr) * KWORDS + lh;
    const unsigned* BpH = Bh + (size_t)(n0 + lr) * KWORDS + lh;
    const unsigned* BpL = Bl + (size_t)(n0 + lr) * KWORDS + lh;

    uint4 rah = *(const uint4*)ApH, ral = *(const uint4*)ApL;
    uint4 rbh = *(const uint4*)BpH, rbl = *(const uint4*)BpL;

    float acc[4][4][4];
    #pragma unroll
    for (int i = 0; i < 4; i++)
        #pragma unroll
        for (int j = 0; j < 4; j++)
            #pragma unroll
            for (int r = 0; r < 4; r++) acc[i][j][r] = 0.0f;

    Ahs[0][lr][lh+0]=rah.x; Ahs[0][lr][lh+1]=rah.y; Ahs[0][lr][lh+2]=rah.z; Ahs[0][lr][lh+3]=rah.w;
    Als[0][lr][lh+0]=ral.x; Als[0][lr][lh+1]=ral.y; Als[0][lr][lh+2]=ral.z; Als[0][lr][lh+3]=ral.w;
    Bhs[0][lr][lh+0]=rbh.x; Bhs[0][lr][lh+1]=rbh.y; Bhs[0][lr][lh+2]=rbh.z; Bhs[0][lr][lh+3]=rbh.w;
    Bls[0][lr][lh+0]=rbl.x; Bls[0][lr][lh+1]=rbl.y; Bls[0][lr][lh+2]=rbl.z; Bls[0][lr][lh+3]=rbl.w;

    const int NSLAB = KWORDS / 8;
    int buf = 0;
    #pragma unroll 1
    for (int t = 0; t < NSLAB; t++) {
        if (t < NSLAB - 1) {
            rah = *(const uint4*)(ApH + (t + 1) * 8);
            ral = *(const uint4*)(ApL + (t + 1) * 8);
            rbh = *(const uint4*)(BpH + (t + 1) * 8);
            rbl = *(const uint4*)(BpL + (t + 1) * 8);
        }
        __syncthreads();

        unsigned bh0[4], bh1[4], bl0[4], bl1[4];
        #pragma unroll
        for (int nf = 0; nf < 4; nf++) {
            int cn = wn * 32 + nf * 8 + g;
            bh0[nf] = Bhs[buf][cn][tg];   bh1[nf] = Bhs[buf][cn][tg + 4];
            bl0[nf] = Bls[buf][cn][tg];   bl1[nf] = Bls[buf][cn][tg + 4];
        }
        #pragma unroll
        for (int mf = 0; mf < 4; mf++) {
            int rm = wm * 64 + mf * 16 + g;
            unsigned ah0 = Ahs[buf][rm][tg],     ah1 = Ahs[buf][rm + 8][tg];
            unsigned ah2 = Ahs[buf][rm][tg + 4], ah3 = Ahs[buf][rm + 8][tg + 4];
            unsigned al0 = Als[buf][rm][tg],     al1 = Als[buf][rm + 8][tg];
            unsigned al2 = Als[buf][rm][tg + 4], al3 = Als[buf][rm + 8][tg + 4];
            #pragma unroll
            for (int nf = 0; nf < 4; nf++) {
                mma16(acc[mf][nf], ah0, ah1, ah2, ah3, bh0[nf], bh1[nf]);
                mma16(acc[mf][nf], ah0, ah1, ah2, ah3, bl0[nf], bl1[nf]);
                mma16(acc[mf][nf], al0, al1, al2, al3, bh0[nf], bh1[nf]);
            }
        }
        if (t < NSLAB - 1) {
            int nb = buf ^ 1;
            Ahs[nb][lr][lh+0]=rah.x; Ahs[nb][lr][lh+1]=rah.y; Ahs[nb][lr][lh+2]=rah.z; Ahs[nb][lr][lh+3]=rah.w;
            Als[nb][lr][lh+0]=ral.x; Als[nb][lr][lh+1]=ral.y; Als[nb][lr][lh+2]=ral.z; Als[nb][lr][lh+3]=ral.w;
            Bhs[nb][lr][lh+0]=rbh.x; Bhs[nb][lr][lh+1]=rbh.y; Bhs[nb][lr][lh+2]=rbh.z; Bhs[nb][lr][lh+3]=rbh.w;
            Bls[nb][lr][lh+0]=rbl.x; Bls[nb][lr][lh+1]=rbl.y; Bls[nb][lr][lh+2]=rbl.z; Bls[nb][lr][lh+3]=rbl.w;
        }
        buf ^= 1;
    }

    #pragma unroll
    for (int mf = 0; mf < 4; mf++) {
        int r0 = m0 + wm * 64 + mf * 16 + g;
        #pragma unroll
        for (int nf = 0; nf < 4; nf++) {
            int j = n0 + wn * 32 + nf * 8 + 2 * tg;
            float v00 = acc[mf][nf][0] + bias[j];
            float v01 = acc[mf][nf][1] + bias[j + 1];
            float v10 = acc[mf][nf][2] + bias[j];
            float v11 = acc[mf][nf][3] + bias[j + 1];
            int r1 = r0 + 8;
            if (MODE == 0) {
                *(float2*)&Cout[(size_t)r0 * HIDDEN + j] = make_float2(v00, v01);
                *(float2*)&Cout[(size_t)r1 * HIDDEN + j] = make_float2(v10, v11);
            } else if (MODE == 1) {
                int h = j >> 6, w = (j & 63) >> 1;
                int b0i = r0 >> 10, nn0 = r0 & 1023;
                int b1i = r1 >> 10, nn1 = r1 & 1023;
                unsigned hw, lw;
                size_t i0 = ((size_t)(b0i * NHEAD + h) * NTOK + nn0) * HW + w;
                splitpack(v00, v01, hw, lw); Ch[i0] = hw; Cl[i0] = lw;
                size_t i1 = ((size_t)(b1i * NHEAD + h) * NTOK + nn1) * HW + w;
                splitpack(v10, v11, hw, lw); Ch[i1] = hw; Cl[i1] = lw;
            } else if (MODE == 2) {
                int h = j >> 6, dd = j & 63;
                int b0i = r0 >> 10, nn0 = r0 & 1023;
                int b1i = r1 >> 10, nn1 = r1 & 1023;
                unsigned short hs, ls;
                size_t base0 = ((size_t)(b0i * NHEAD + h) * HD + dd) * NTOK;
                size_t base1 = ((size_t)(b1i * NHEAD + h) * HD + dd) * NTOK;
                split1(v00, hs, ls); Vh[base0 + nn0]        = hs; Vl[base0 + nn0]        = ls;
                split1(v01, hs, ls); Vh[base0 + NTOK + nn0] = hs; Vl[base0 + NTOK + nn0] = ls;
                split1(v10, hs, ls); Vh[base1 + nn1]        = hs; Vl[base1 + nn1]        = ls;
                split1(v11, hs, ls); Vh[base1 + NTOK + nn1] = hs; Vl[base1 + NTOK + nn1] = ls;
            } else {  // MODE 3: tokens = . + pb + pe, split
                const float* pe0 = d_pe + (size_t)(r0 & 1023) * HIDDEN + j;
                const float* pe1 = d_pe + (size_t)(r1 & 1023) * HIDDEN + j;
                unsigned hw, lw;
                splitpack(v00 + pe0[0], v01 + pe0[1], hw, lw);
                size_t w0 = (size_t)r0 * KW + (j >> 1);
                Ch[w0] = hw; Cl[w0] = lw;
                splitpack(v10 + pe1[0], v11 + pe1[1], hw, lw);
                size_t w1 = (size_t)r1 * KW + (j >> 1);
                Ch[w1] = hw; Cl[w1] = lw;
            }
        }
    }
}

// ================= flash attention, bf16-split MMAs, register softmax ============
__global__ __launch_bounds__(256, 2)
void attn_mma(const float* __restrict__ lam_p) {
    extern __shared__ unsigned smw[];
    unsigned* Qh = smw;                  // [64][36]
    unsigned* Ql = Qh + 64 * 36;
    unsigned* Kh = Ql + 64 * 36;         // [c][d-word]
    unsigned* Kl = Kh + 64 * 36;
    unsigned* Vh = Kl + 64 * 36;         // V^T: [d][c-word]
    unsigned* Vl = Vh + 64 * 36;
    unsigned* Ph = Vl + 64 * 36;         // [r][c-word]
    unsigned* Pl = Ph + 64 * 36;
    float* msh = (float*)(Pl + 64 * 36);
    float* lsh = msh + 64;
    float* gq  = lsh + 64;
    float* gk  = gq + 64;
    float* rx  = gk + 64;                // [2][64] half row-max
    float* rs  = rx + 128;               // [2][64] half row-sum

    const int tid = threadIdx.x;
    const int lane = tid & 31, wid = tid >> 5;
    const int wm = wid & 3, wn = wid >> 2;
    const int g = lane >> 2, tg = lane & 3;
    const int n0 = blockIdx.x * 64;
    const int h = blockIdx.y, b = blockIdx.z;
    const float lam = *lam_p;
    const int rm = wm * 16 + g;

    const size_t qkbase = (size_t)(b * NHEAD + h) * NTOK * HW;
    const size_t vbase  = (size_t)(b * NHEAD + h) * HD * NTOK;   // ushort units

    const int lr = tid >> 2;           // 0..63
    const int wo = (tid & 3) * 8;      // word offset 0..24

    {
        size_t o = qkbase + (size_t)(n0 + lr) * HW + wo;
        *(uint4*)&Qh[lr * 36 + wo]     = *(const uint4*)(d_qh2 + o);
        *(uint4*)&Qh[lr * 36 + wo + 4] = *(const uint4*)(d_qh2 + o + 4);
        *(uint4*)&Ql[lr * 36 + wo]     = *(const uint4*)(d_ql2 + o);
        *(uint4*)&Ql[lr * 36 + wo + 4] = *(const uint4*)(d_ql2 + o + 4);
    }
    if (tid < 64) {
        msh[tid] = -CUDART_INF_F;
        lsh[tid] = 0.0f;
        gq[tid]  = d_g[b * NTOK + n0 + tid];
    }

    float o[4][4];
    #pragma unroll
    for (int nf = 0; nf < 4; nf++)
        #pragma unroll
        for (int r = 0; r < 4; r++) o[nf][r] = 0.0f;

    for (int k0 = 0; k0 < NTOK; k0 += 64) {
        __syncthreads();
        {
            size_t ko = qkbase + (size_t)(k0 + lr) * HW + wo;
            *(uint4*)&Kh[lr * 36 + wo]     = *(const uint4*)(d_kh2 + ko);
            *(uint4*)&Kh[lr * 36 + wo + 4] = *(const uint4*)(d_kh2 + ko + 4);
            *(uint4*)&Kl[lr * 36 + wo]     = *(const uint4*)(d_kl2 + ko);
            *(uint4*)&Kl[lr * 36 + wo + 4] = *(const uint4*)(d_kl2 + ko + 4);
            size_t vo = vbase + (size_t)lr * NTOK + k0 + 2 * wo;
            *(uint4*)&Vh[lr * 36 + wo]     = *(const uint4*)(d_vth + vo);
            *(uint4*)&Vh[lr * 36 + wo + 4] = *(const uint4*)(d_vth + vo + 8);
            *(uint4*)&Vl[lr * 36 + wo]     = *(const uint4*)(d_vtl + vo);
            *(uint4*)&Vl[lr * 36 + wo + 4] = *(const uint4*)(d_vtl + vo + 8);
        }
        if (tid < 64) gk[tid] = d_g[b * NTOK + k0 + tid];
        __syncthreads();

        // S = Q K^T (hi/lo split, 3 MMAs per pair)
        float s[4][4];
        #pragma unroll
        for (int nf = 0; nf < 4; nf++)
            #pragma unroll
            for (int r = 0; r < 4; r++) s[nf][r] = 0.0f;
        #pragma unroll
        for (int s8 = 0; s8 < 4; s8++) {
            unsigned ah0 = Qh[rm * 36 + s8 * 8 + tg];
            unsigned ah1 = Qh[(rm + 8) * 36 + s8 * 8 + tg];
            unsigned ah2 = Qh[rm * 36 + s8 * 8 + 4 + tg];
            unsigned ah3 = Qh[(rm + 8) * 36 + s8 * 8 + 4 + tg];
            unsigned al0 = Ql[rm * 36 + s8 * 8 + tg];
            unsigned al1 = Ql[(rm + 8) * 36 + s8 * 8 + tg];
            unsigned al2 = Ql[rm * 36 + s8 * 8 + 4 + tg];
            unsigned al3 = Ql[(rm + 8) * 36 + s8 * 8 + 4 + tg];
            #pragma unroll
            for (int nf = 0; nf < 4; nf++) {
                int cn = wn * 32 + nf * 8 + g;
                unsigned bh0 = Kh[cn * 36 + s8 * 8 + tg];
                unsigned bh1 = Kh[cn * 36 + s8 * 8 + 4 + tg];
                unsigned bl0 = Kl[cn * 36 + s8 * 8 + tg];
                unsigned bl1 = Kl[cn * 36 + s8 * 8 + 4 + tg];
                mma16(s[nf], ah0, ah1, ah2, ah3, bh0, bh1);
                mma16(s[nf], ah0, ah1, ah2, ah3, bl0, bl1);
                mma16(s[nf], al0, al1, al2, al3, bh0, bh1);
            }
        }

        // scale + bias in registers, then register softmax
        float mx0 = -CUDART_INF_F, mx1 = -CUDART_INF_F;
        {
            float gq0 = gq[rm], gq1 = gq[rm + 8];
            #pragma unroll
            for (int nf = 0; nf < 4; nf++) {
                int c0 = wn * 32 + nf * 8 + 2 * tg;
                float gk0 = gk[c0], gk1 = gk[c0 + 1];
                s[nf][0] = s[nf][0] * 0.125f + lam * gq0 * gk0;
                s[nf][1] = s[nf][1] * 0.125f + lam * gq0 * gk1;
                s[nf][2] = s[nf][2] * 0.125f + lam * gq1 * gk0;
                s[nf][3] = s[nf][3] * 0.125f + lam * gq1 * gk1;
                mx0 = fmaxf(mx0, fmaxf(s[nf][0], s[nf][1]));
                mx1 = fmaxf(mx1, fmaxf(s[nf][2], s[nf][3]));
            }
        }
        mx0 = fmaxf(mx0, __shfl_xor_sync(0xffffffffu, mx0, 1));
        mx0 = fmaxf(mx0, __shfl_xor_sync(0xffffffffu, mx0, 2));
        mx1 = fmaxf(mx1, __shfl_xor_sync(0xffffffffu, mx1, 1));
        mx1 = fmaxf(mx1, __shfl_xor_sync(0xffffffffu, mx1, 2));
        if (tg == 0) {
            rx[wn * 64 + rm]     = mx0;
            rx[wn * 64 + rm + 8] = mx1;
        }
        __syncthreads();

        float m_old0 = msh[rm], m_old1 = msh[rm + 8];
        float mn0 = fmaxf(m_old0, fmaxf(rx[rm], rx[64 + rm]));
        float mn1 = fmaxf(m_old1, fmaxf(rx[rm + 8], rx[64 + rm + 8]));
        float alpha0 = __expf(m_old0 - mn0);
        float alpha1 = __expf(m_old1 - mn1);

        float sum0 = 0.0f, sum1 = 0.0f;
        #pragma unroll
        for (int nf = 0; nf < 4; nf++) {
            s[nf][0] = __expf(s[nf][0] - mn0);
            s[nf][1] = __expf(s[nf][1] - mn0);
            s[nf][2] = __expf(s[nf][2] - mn1);
            s[nf][3] = __expf(s[nf][3] - mn1);
            sum0 += s[nf][0] + s[nf][1];
            sum1 += s[nf][2] + s[nf][3];
            unsigned hw, lw;
            int w = 16 * wn + 4 * nf + tg;
            splitpack(s[nf][0], s[nf][1], hw, lw);
            Ph[rm * 36 + w] = hw; Pl[rm * 36 + w] = lw;
            splitpack(s[nf][2], s[nf][3], hw, lw);
            Ph[(rm + 8) * 36 + w] = hw; Pl[(rm + 8) * 36 + w] = lw;
        }
        sum0 += __shfl_xor_sync(0xffffffffu, sum0, 1);
        sum0 += __shfl_xor_sync(0xffffffffu, sum0, 2);
        sum1 += __shfl_xor_sync(0xffffffffu, sum1, 1);
        sum1 += __shfl_xor_sync(0xffffffffu, sum1, 2);
        if (tg == 0) {
            rs[wn * 64 + rm]     = sum0;
            rs[wn * 64 + rm + 8] = sum1;
        }
        __syncthreads();
        if (wn == 0 && tg == 0) {
            lsh[rm]     = lsh[rm] * alpha0 + rs[rm] + rs[64 + rm];
            msh[rm]     = mn0;
            lsh[rm + 8] = lsh[rm + 8] * alpha1 + rs[rm + 8] + rs[64 + rm + 8];
            msh[rm + 8] = mn1;
        }

        // rescale accumulator, then O += P V
        #pragma unroll
        for (int nf = 0; nf < 4; nf++) {
            o[nf][0] *= alpha0; o[nf][1] *= alpha0;
            o[nf][2] *= alpha1; o[nf][3] *= alpha1;
        }
        #pragma unroll
        for (int s8 = 0; s8 < 4; s8++) {
            unsigned ah0 = Ph[rm * 36 + s8 * 8 + tg];
            unsigned ah1 = Ph[(rm + 8) * 36 + s8 * 8 + tg];
            unsigned ah2 = Ph[rm * 36 + s8 * 8 + 4 + tg];
            unsigned ah3 = Ph[(rm + 8) * 36 + s8 * 8 + 4 + tg];
            unsigned al0 = Pl[rm * 36 + s8 * 8 + tg];
            unsigned al1 = Pl[(rm + 8) * 36 + s8 * 8 + tg];
            unsigned al2 = Pl[rm * 36 + s8 * 8 + 4 + tg];
            unsigned al3 = Pl[(rm + 8) * 36 + s8 * 8 + 4 + tg];
            #pragma unroll
            for (int nf = 0; nf < 4; nf++) {
                int cn = wn * 32 + nf * 8 + g;
                unsigned bh0 = Vh[cn * 36 + s8 * 8 + tg];
                unsigned bh1 = Vh[cn * 36 + s8 * 8 + 4 + tg];
                unsigned bl0 = Vl[cn * 36 + s8 * 8 + tg];
                unsigned bl1 = Vl[cn * 36 + s8 * 8 + 4 + tg];
                mma16(o[nf], ah0, ah1, ah2, ah3, bh0, bh1);
                mma16(o[nf], ah0, ah1, ah2, ah3, bl0, bl1);
                mma16(o[nf], al0, al1, al2, al3, bh0, bh1);
            }
        }
    }
    __syncthreads();

    {
        float li0 = 1.0f / lsh[rm], li1 = 1.0f / lsh[rm + 8];
        #pragma unroll
        for (int nf = 0; nf < 4; nf++) {
            int j = wn * 32 + nf * 8 + 2 * tg;
            unsigned hw, lw;
            size_t w0 = ((size_t)b * NTOK + n0 + rm) * KW + ((h * HD + j) >> 1);
            splitpack(o[nf][0] * li0, o[nf][1] * li0, hw, lw);
            d_ath[w0] = hw; d_atl[w0] = lw;
            size_t w1 = ((size_t)b * NTOK + n0 + rm + 8) * KW + ((h * HD + j) >> 1);
            splitpack(o[nf][2] * li1, o[nf][3] * li1, hw, lw);
            d_ath[w1] = hw; d_atl[w1] = lw;
        }
    }
}

// ---------------- launch ----------------------------------------------------------
extern "C" void kernel_launch(void* const* d_in, const int* in_sizes, int n_in,
                              void* d_out, int out_size) {
    const float* feat = (const float*)d_in[0];
    const float* I    = (const float*)d_in[1];
    const float* pw   = (const float*)d_in[2];
    const float* pb   = (const float*)d_in[3];
    const float* wq   = (const float*)d_in[4];
    const float* bq   = (const float*)d_in[5];
    const float* wk   = (const float*)d_in[6];
    const float* bk   = (const float*)d_in[7];
    const float* wv   = (const float*)d_in[8];
    const float* bv   = (const float*)d_in[9];
    const float* wo   = (const float*)d_in[10];
    const float* bo   = (const float*)d_in[11];
    const float* lam  = (const float*)d_in[12];
    float* out = (float*)d_out;

    unsigned *tokh, *tokl, *ath, *atl, *fth, *ftl, *pwh, *pwl;
    unsigned *wqh, *wql, *wkh, *wkl, *wvh, *wvl, *woh, *wol;
    unsigned *qh2, *ql2, *kh2, *kl2;
    unsigned short *vth, *vtl;
    cudaGetSymbolAddress((void**)&tokh, d_tokh);
    cudaGetSymbolAddress((void**)&tokl, d_tokl);
    cudaGetSymbolAddress((void**)&ath,  d_ath);
    cudaGetSymbolAddress((void**)&atl,  d_atl);
    cudaGetSymbolAddress((void**)&fth,  d_fth);
    cudaGetSymbolAddress((void**)&ftl,  d_ftl);
    cudaGetSymbolAddress((void**)&pwh,  d_pwh);
    cudaGetSymbolAddress((void**)&pwl,  d_pwl);
    cudaGetSymbolAddress((void**)&wqh,  d_wqh);
    cudaGetSymbolAddress((void**)&wql,  d_wql);
    cudaGetSymbolAddress((void**)&wkh,  d_wkh);
    cudaGetSymbolAddress((void**)&wkl,  d_wkl);
    cudaGetSymbolAddress((void**)&wvh,  d_wvh);
    cudaGetSymbolAddress((void**)&wvl,  d_wvl);
    cudaGetSymbolAddress((void**)&woh,  d_woh);
    cudaGetSymbolAddress((void**)&wol,  d_wol);
    cudaGetSymbolAddress((void**)&qh2,  d_qh2);
    cudaGetSymbolAddress((void**)&ql2,  d_ql2);
    cudaGetSymbolAddress((void**)&kh2,  d_kh2);
    cudaGetSymbolAddress((void**)&kl2,  d_kl2);
    cudaGetSymbolAddress((void**)&vth,  d_vth);
    cudaGetSymbolAddress((void**)&vtl,  d_vtl);

    pe_kernel<<<(NTOK * HIDDEN + 255) / 256, 256>>>();
    gauss_kernel<<<(M_TOT + 255) / 256, 256>>>(I);

    // splits
    dim3 wsb(32, 8);
    fsplit_kernel<<<dim3(NTOK / 32, C_IN / 32, BATCH), wsb>>>(
        feat, (unsigned short*)fth, (unsigned short*)ftl);
    wsplitg_kernel<<<dim3(HIDDEN / 32, C_IN / 32), wsb>>>(
        pw, (unsigned short*)pwh, (unsigned short*)pwl, C_IN, HIDDEN);
    dim3 wsg(HIDDEN / 32, HIDDEN / 32);
    wsplitg_kernel<<<wsg, wsb>>>(wq, (unsigned short*)wqh, (unsigned short*)wql, HIDDEN, HIDDEN);
    wsplitg_kernel<<<wsg, wsb>>>(wk, (unsigned short*)wkh, (unsigned short*)wkl, HIDDEN, HIDDEN);
    wsplitg_kernel<<<wsg, wsb>>>(wv, (unsigned short*)wvh, (unsigned short*)wvl, HIDDEN, HIDDEN);
    wsplitg_kernel<<<wsg, wsb>>>(wo, (unsigned short*)woh, (unsigned short*)wol, HIDDEN, HIDDEN);

    dim3 gBig(HIDDEN / 128, M_TOT / 128);
    // projection: tokens = feat^T @ pw + pb + pe (MODE 3, K=256)
    gemm_bf16<3, CW><<<gBig, 256>>>(fth, ftl, pwh, pwl, pb, nullptr, tokh, tokl, nullptr, nullptr);

    // QKV
    gemm_bf16<1, KW><<<gBig, 256>>>(tokh, tokl, wqh, wql, bq, nullptr, qh2, ql2, nullptr, nullptr);
    gemm_bf16<1, KW><<<gBig, 256>>>(tokh, tokl, wkh, wkl, bk, nullptr, kh2, kl2, nullptr, nullptr);
    gemm_bf16<2, KW><<<gBig, 256>>>(tokh, tokl, wvh, wvl, bv, nullptr, nullptr, nullptr, vth, vtl);

    // attention (register softmax)
    size_t smem = (8 * 64 * 36) * 4 + (4 * 64 + 2 * 128) * 4;   // 75776 B
    cudaFuncSetAttribute(attn_mma, cudaFuncAttributeMaxDynamicSharedMemorySize,
                         (int)smem);
    attn_mma<<<dim3(NTOK / 64, NHEAD, BATCH), 256, smem>>>(lam);

    // output projection
    gemm_bf16<0, KW><<<gBig, 256>>>(ath, atl, woh, wol, bo, out, nullptr, nullptr, nullptr, nullptr);
}

// round 15
// speedup vs baseline: 2.3102x; 1.0865x over previous
#include <cuda_runtime.h>
#include <cuda_bf16.h>
#include <math.h>
#include <math_constants.h>

#define HIDDEN 768
#define NHEAD  12
#define HD     64
#define BATCH  8
#define NTOK   1024
#define C_IN   256
#define M_TOT  (BATCH * NTOK)
#define KW     384            // HIDDEN/2 words (bf16x2 along k)
#define CW     128            // C_IN/2 words
#define HW     32             // HD/2 words per head-row

// ---------------- scratch (static device arrays; no allocation) ----------------
__device__ float d_g[M_TOT];
__device__ float d_pe[NTOK * HIDDEN];
__device__ unsigned d_tokh[M_TOT * KW];
__device__ unsigned d_tokl[M_TOT * KW];
__device__ unsigned d_ath[M_TOT * KW];
__device__ unsigned d_atl[M_TOT * KW];
__device__ unsigned d_fth[M_TOT * CW];
__device__ unsigned d_ftl[M_TOT * CW];
__device__ unsigned d_qh2[BATCH * NHEAD * NTOK * HW];
__device__ unsigned d_ql2[BATCH * NHEAD * NTOK * HW];
__device__ unsigned d_kh2[BATCH * NHEAD * NTOK * HW];
__device__ unsigned d_kl2[BATCH * NHEAD * NTOK * HW];
__device__ unsigned short d_vth[BATCH * NHEAD * HD * NTOK];
__device__ unsigned short d_vtl[BATCH * NHEAD * HD * NTOK];
__device__ unsigned d_pwh[HIDDEN * CW];
__device__ unsigned d_pwl[HIDDEN * CW];
__device__ unsigned d_wqh[HIDDEN * KW];
__device__ unsigned d_wql[HIDDEN * KW];
__device__ unsigned d_wkh[HIDDEN * KW];
__device__ unsigned d_wkl[HIDDEN * KW];
__device__ unsigned d_wvh[HIDDEN * KW];
__device__ unsigned d_wvl[HIDDEN * KW];
__device__ unsigned d_woh[HIDDEN * KW];
__device__ unsigned d_wol[HIDDEN * KW];

// ---------------- helpers --------------------------------------------------------
__device__ __forceinline__ void splitpack(float x0, float x1, unsigned& h, unsigned& l) {
    __nv_bfloat16 h0 = __float2bfloat16_rn(x0), h1 = __float2bfloat16_rn(x1);
    float r0 = x0 - __bfloat162float(h0), r1 = x1 - __bfloat162float(h1);
    __nv_bfloat16 l0 = __float2bfloat16_rn(r0), l1 = __float2bfloat16_rn(r1);
    h = ((unsigned)__bfloat16_as_ushort(h1) << 16) | (unsigned)__bfloat16_as_ushort(h0);
    l = ((unsigned)__bfloat16_as_ushort(l1) << 16) | (unsigned)__bfloat16_as_ushort(l0);
}
__device__ __forceinline__ void split1(float x, unsigned short& h, unsigned short& l) {
    __nv_bfloat16 hb = __float2bfloat16_rn(x);
    __nv_bfloat16 lb = __float2bfloat16_rn(x - __bfloat162float(hb));
    h = __bfloat16_as_ushort(hb);
    l = __bfloat16_as_ushort(lb);
}

__device__ __forceinline__ void mma16(float* c, unsigned a0, unsigned a1,
                                      unsigned a2, unsigned a3,
                                      unsigned b0, unsigned b1) {
    asm volatile(
        "mma.sync.aligned.m16n8k16.row.col.f32.bf16.bf16.f32 "
        "{%0,%1,%2,%3}, {%4,%5,%6,%7}, {%8,%9}, {%0,%1,%2,%3};"
        : "+f"(c[0]), "+f"(c[1]), "+f"(c[2]), "+f"(c[3])
        : "r"(a0), "r"(a1), "r"(a2), "r"(a3), "r"(b0), "r"(b1));
}

// ---------------- positional encoding -------------------------------------------
__global__ void pe_kernel() {
    int idx = blockIdx.x * blockDim.x + threadIdx.x;
    if (idx >= NTOK * HIDDEN) return;
    int n = idx / HIDDEN, d = idx % HIDDEN;
    int i2 = d & ~1;
    float div = expf((float)i2 * -0.011992630692677323f);  // -ln(10000)/768
    float ph = (float)n * div;
    d_pe[idx] = (d & 1) ? cosf(ph) : sinf(ph);
}

// ---------------- gaussian weights -----------------------------------------------
__global__ void gauss_kernel(const float* __restrict__ I) {
    int idx = blockIdx.x * blockDim.x + threadIdx.x;
    if (idx >= M_TOT) return;
    float x = I[idx];
    float x2 = x * x;
    const float d0 = 2.0f * 0.25f + 1e-5f;
    const float d1 = 2.0f * 1.00f + 1e-5f;
    const float d2 = 2.0f * 4.00f + 1e-5f;
    float g = (expf(-x2 / d0) + expf(-x2 / d1) + expf(-x2 / d2)) * (1.0f / 3.0f);
    d_g[idx] = g;
}

// ------------- generic weight transpose + split (single) --------------------------
__global__ void wsplitg_kernel(const float* __restrict__ W,
                               unsigned short* __restrict__ Th,
                               unsigned short* __restrict__ Tl,
                               int Kdim, int Ndim) {
    __shared__ float tile[32][33];
    int tx = threadIdx.x, ty = threadIdx.y;      // 32 x 8
    int n0 = blockIdx.x * 32, k0 = blockIdx.y * 32;
    #pragma unroll
    for (int r = 0; r < 32; r += 8)
        tile[ty + r][tx] = W[(size_t)(k0 + ty + r) * Ndim + n0 + tx];
    __syncthreads();
    #pragma unroll
    for (int r = 0; r < 32; r += 8) {
        float x = tile[tx][ty + r];
        unsigned short hs, ls;
        split1(x, hs, ls);
        size_t o = (size_t)(n0 + ty + r) * Kdim + k0 + tx;
        Th[o] = hs;
        Tl[o] = ls;
    }
}

// ------------- fused 4-way weight transpose + split (768x768, z selects weight) ---
__global__ void wsplit4_kernel(const float* __restrict__ w0, const float* __restrict__ w1,
                               const float* __restrict__ w2, const float* __restrict__ w3,
                               unsigned short* __restrict__ t0h, unsigned short* __restrict__ t0l,
                               unsigned short* __restrict__ t1h, unsigned short* __restrict__ t1l,
                               unsigned short* __restrict__ t2h, unsigned short* __restrict__ t2l,
                               unsigned short* __restrict__ t3h, unsigned short* __restrict__ t3l) {
    __shared__ float tile[32][33];
    int z = blockIdx.z;
    const float* W = (z == 0) ? w0 : (z == 1) ? w1 : (z == 2) ? w2 : w3;
    unsigned short* Th = (z == 0) ? t0h : (z == 1) ? t1h : (z == 2) ? t2h : t3h;
    unsigned short* Tl = (z == 0) ? t0l : (z == 1) ? t1l : (z == 2) ? t2l : t3l;
    int tx = threadIdx.x, ty = threadIdx.y;
    int n0 = blockIdx.x * 32, k0 = blockIdx.y * 32;
    #pragma unroll
    for (int r = 0; r < 32; r += 8)
        tile[ty + r][tx] = W[(size_t)(k0 + ty + r) * HIDDEN + n0 + tx];
    __syncthreads();
    #pragma unroll
    for (int r = 0; r < 32; r += 8) {
        float x = tile[tx][ty + r];
        unsigned short hs, ls;
        split1(x, hs, ls);
        size_t o = (size_t)(n0 + ty + r) * HIDDEN + k0 + tx;
        Th[o] = hs;
        Tl[o] = ls;
    }
}

// ------------- feat transpose + split ---------------------------------------------
__global__ void fsplit_kernel(const float* __restrict__ feat,
                              unsigned short* __restrict__ Fh,
                              unsigned short* __restrict__ Fl) {
    __shared__ float tile[32][33];
    int tx = threadIdx.x, ty = threadIdx.y;
    int n0 = blockIdx.x * 32, c0 = blockIdx.y * 32, b = blockIdx.z;
    const float* fb = feat + (size_t)b * C_IN * NTOK;
    #pragma unroll
    for (int r = 0; r < 32; r += 8)
        tile[ty + r][tx] = fb[(size_t)(c0 + ty + r) * NTOK + n0 + tx];
    __syncthreads();
    #pragma unroll
    for (int r = 0; r < 32; r += 8) {
        float x = tile[tx][ty + r];
        unsigned short hs, ls;
        split1(x, hs, ls);
        size_t o = ((size_t)b * NTOK + n0 + ty + r) * C_IN + c0 + tx;
        Fh[o] = hs;
        Fl[o] = ls;
    }
}

// ================= bf16-split tensor-core GEMM =====================================
template <int MODE, int KWORDS>
__global__ __launch_bounds__(256, 2)
void gemm_bf16(const unsigned* __restrict__ Ah, const unsigned* __restrict__ Al,
               const unsigned* __restrict__ Bh, const unsigned* __restrict__ Bl,
               const float* __restrict__ bias, float* __restrict__ Cout,
               unsigned* __restrict__ Ch, unsigned* __restrict__ Cl,
               unsigned short* __restrict__ Vh, unsigned short* __restrict__ Vl) {
    __shared__ unsigned Ahs[2][128][9], Als[2][128][9];
    __shared__ unsigned Bhs[2][128][9], Bls[2][128][9];
    const int tid = threadIdx.x;
    const int lane = tid & 31, wid = tid >> 5;
    const int wm = wid & 1, wn = wid >> 1;
    const int g = lane >> 2, tg = lane & 3;
    const int n0 = blockIdx.x * 128, m0 = blockIdx.y * 128;

    const int lr = tid >> 1;
    const int lh = (tid & 1) * 4;

    const unsigned* ApH = Ah + (size_t)(m0 + lr) * KWORDS + lh;
    const unsigned* ApL = Al + (size_t)(m0 + lr) * KWORDS + lh;
    const unsigned* BpH = Bh + (size_t)(n0 + lr) * KWORDS + lh;
    const unsigned* BpL = Bl + (size_t)(n0 + lr) * KWORDS + lh;

    uint4 rah = *(const uint4*)ApH, ral = *(const uint4*)ApL;
    uint4 rbh = *(const uint4*)BpH, rbl = *(const uint4*)BpL;

    float acc[4][4][4];
    #pragma unroll
    for (int i = 0; i < 4; i++)
        #pragma unroll
        for (int j = 0; j < 4; j++)
            #pragma unroll
            for (int r = 0; r < 4; r++) acc[i][j][r] = 0.0f;

    Ahs[0][lr][lh+0]=rah.x; Ahs[0][lr][lh+1]=rah.y; Ahs[0][lr][lh+2]=rah.z; Ahs[0][lr][lh+3]=rah.w;
    Als[0][lr][lh+0]=ral.x; Als[0][lr][lh+1]=ral.y; Als[0][lr][lh+2]=ral.z; Als[0][lr][lh+3]=ral.w;
    Bhs[0][lr][lh+0]=rbh.x; Bhs[0][lr][lh+1]=rbh.y; Bhs[0][lr][lh+2]=rbh.z; Bhs[0][lr][lh+3]=rbh.w;
    Bls[0][lr][lh+0]=rbl.x; Bls[0][lr][lh+1]=rbl.y; Bls[0][lr][lh+2]=rbl.z; Bls[0][lr][lh+3]=rbl.w;

    const int NSLAB = KWORDS / 8;
    int buf = 0;
    #pragma unroll 1
    for (int t = 0; t < NSLAB; t++) {
        if (t < NSLAB - 1) {
            rah = *(const uint4*)(ApH + (t + 1) * 8);
            ral = *(const uint4*)(ApL + (t + 1) * 8);
            rbh = *(const uint4*)(BpH + (t + 1) * 8);
            rbl = *(const uint4*)(BpL + (t + 1) * 8);
        }
        __syncthreads();

        unsigned bh0[4], bh1[4], bl0[4], bl1[4];
        #pragma unroll
        for (int nf = 0; nf < 4; nf++) {
            int cn = wn * 32 + nf * 8 + g;
            bh0[nf] = Bhs[buf][cn][tg];   bh1[nf] = Bhs[buf][cn][tg + 4];
            bl0[nf] = Bls[buf][cn][tg];   bl1[nf] = Bls[buf][cn][tg + 4];
        }
        #pragma unroll
        for (int mf = 0; mf < 4; mf++) {
            int rm = wm * 64 + mf * 16 + g;
            unsigned ah0 = Ahs[buf][rm][tg],     ah1 = Ahs[buf][rm + 8][tg];
            unsigned ah2 = Ahs[buf][rm][tg + 4], ah3 = Ahs[buf][rm + 8][tg + 4];
            unsigned al0 = Als[buf][rm][tg],     al1 = Als[buf][rm + 8][tg];
            unsigned al2 = Als[buf][rm][tg + 4], al3 = Als[buf][rm + 8][tg + 4];
            #pragma unroll
            for (int nf = 0; nf < 4; nf++) {
                mma16(acc[mf][nf], ah0, ah1, ah2, ah3, bh0[nf], bh1[nf]);
                mma16(acc[mf][nf], ah0, ah1, ah2, ah3, bl0[nf], bl1[nf]);
                mma16(acc[mf][nf], al0, al1, al2, al3, bh0[nf], bh1[nf]);
            }
        }
        if (t < NSLAB - 1) {
            int nb = buf ^ 1;
            Ahs[nb][lr][lh+0]=rah.x; Ahs[nb][lr][lh+1]=rah.y; Ahs[nb][lr][lh+2]=rah.z; Ahs[nb][lr][lh+3]=rah.w;
            Als[nb][lr][lh+0]=ral.x; Als[nb][lr][lh+1]=ral.y; Als[nb][lr][lh+2]=ral.z; Als[nb][lr][lh+3]=ral.w;
            Bhs[nb][lr][lh+0]=rbh.x; Bhs[nb][lr][lh+1]=rbh.y; Bhs[nb][lr][lh+2]=rbh.z; Bhs[nb][lr][lh+3]=rbh.w;
            Bls[nb][lr][lh+0]=rbl.x; Bls[nb][lr][lh+1]=rbl.y; Bls[nb][lr][lh+2]=rbl.z; Bls[nb][lr][lh+3]=rbl.w;
        }
        buf ^= 1;
    }

    #pragma unroll
    for (int mf = 0; mf < 4; mf++) {
        int r0 = m0 + wm * 64 + mf * 16 + g;
        #pragma unroll
        for (int nf = 0; nf < 4; nf++) {
            int j = n0 + wn * 32 + nf * 8 + 2 * tg;
            float v00 = acc[mf][nf][0] + bias[j];
            float v01 = acc[mf][nf][1] + bias[j + 1];
            float v10 = acc[mf][nf][2] + bias[j];
            float v11 = acc[mf][nf][3] + bias[j + 1];
            int r1 = r0 + 8;
            if (MODE == 0) {
                *(float2*)&Cout[(size_t)r0 * HIDDEN + j] = make_float2(v00, v01);
                *(float2*)&Cout[(size_t)r1 * HIDDEN + j] = make_float2(v10, v11);
            } else if (MODE == 1) {
                int h = j >> 6, w = (j & 63) >> 1;
                int b0i = r0 >> 10, nn0 = r0 & 1023;
                int b1i = r1 >> 10, nn1 = r1 & 1023;
                unsigned hw, lw;
                size_t i0 = ((size_t)(b0i * NHEAD + h) * NTOK + nn0) * HW + w;
                splitpack(v00, v01, hw, lw); Ch[i0] = hw; Cl[i0] = lw;
                size_t i1 = ((size_t)(b1i * NHEAD + h) * NTOK + nn1) * HW + w;
                splitpack(v10, v11, hw, lw); Ch[i1] = hw; Cl[i1] = lw;
            } else if (MODE == 2) {
                int h = j >> 6, dd = j & 63;
                int b0i = r0 >> 10, nn0 = r0 & 1023;
                int b1i = r1 >> 10, nn1 = r1 & 1023;
                unsigned short hs, ls;
                size_t base0 = ((size_t)(b0i * NHEAD + h) * HD + dd) * NTOK;
                size_t base1 = ((size_t)(b1i * NHEAD + h) * HD + dd) * NTOK;
                split1(v00, hs, ls); Vh[base0 + nn0]        = hs; Vl[base0 + nn0]        = ls;
                split1(v01, hs, ls); Vh[base0 + NTOK + nn0] = hs; Vl[base0 + NTOK + nn0] = ls;
                split1(v10, hs, ls); Vh[base1 + nn1]        = hs; Vl[base1 + nn1]        = ls;
                split1(v11, hs, ls); Vh[base1 + NTOK + nn1] = hs; Vl[base1 + NTOK + nn1] = ls;
            } else {  // MODE 3: tokens = . + pb + pe, split
                const float* pe0 = d_pe + (size_t)(r0 & 1023) * HIDDEN + j;
                const float* pe1 = d_pe + (size_t)(r1 & 1023) * HIDDEN + j;
                unsigned hw, lw;
                splitpack(v00 + pe0[0], v01 + pe0[1], hw, lw);
                size_t w0 = (size_t)r0 * KW + (j >> 1);
                Ch[w0] = hw; Cl[w0] = lw;
                splitpack(v10 + pe1[0], v11 + pe1[1], hw, lw);
                size_t w1 = (size_t)r1 * KW + (j >> 1);
                Ch[w1] = hw; Cl[w1] = lw;
            }
        }
    }
}

// ================= flash attention: 128-row q-tile, P & softmax in registers =====
// 8 warps, warp wm owns rows wm*16..+15, ALL 64 columns.
// S C-fragment (g, 8nf+2tg) == PV A-fragment (nf=2*s8) -> P never hits smem.
__global__ __launch_bounds__(256)
void attn_mma(const float* __restrict__ lam_p) {
    extern __shared__ unsigned smw[];
    unsigned* Qh = smw;                   // [128][36]
    unsigned* Ql = Qh + 128 * 36;
    unsigned* Kh = Ql + 128 * 36;         // [64][36]  (row=c, word=d)
    unsigned* Kl = Kh + 64 * 36;
    unsigned* Vh = Kl + 64 * 36;          // V^T: [64][36] (row=d, word=c)
    unsigned* Vl = Vh + 64 * 36;
    float* gq = (float*)(Vl + 64 * 36);   // [128]
    float* gk = gq + 128;                 // [64]

    const int tid = threadIdx.x;
    const int lane = tid & 31, wm = tid >> 5;
    const int g = lane >> 2, tg = lane & 3;
    const int n0 = blockIdx.x * 128;
    const int h = blockIdx.y, b = blockIdx.z;
    const float lam = *lam_p;
    const int rm = wm * 16 + g;

    const size_t qkbase = (size_t)(b * NHEAD + h) * NTOK * HW;
    const size_t vbase  = (size_t)(b * NHEAD + h) * HD * NTOK;   // ushort units

    // load Q: 2 threads/row, 16 words each
    {
        int lr = tid >> 1, w0 = (tid & 1) * 16;
        size_t o = qkbase + (size_t)(n0 + lr) * HW + w0;
        #pragma unroll
        for (int i = 0; i < 16; i += 4) {
            *(uint4*)&Qh[lr * 36 + w0 + i] = *(const uint4*)(d_qh2 + o + i);
            *(uint4*)&Ql[lr * 36 + w0 + i] = *(const uint4*)(d_ql2 + o + i);
        }
    }
    if (tid < 128) gq[tid] = d_g[b * NTOK + n0 + tid];

    float m0 = -CUDART_INF_F, m1 = -CUDART_INF_F;
    float l0 = 0.0f, l1 = 0.0f;
    float o[8][4];
    #pragma unroll
    for (int nf = 0; nf < 8; nf++)
        #pragma unroll
        for (int r = 0; r < 4; r++) o[nf][r] = 0.0f;

    const int lr = tid >> 2;           // 0..63
    const int wo = (tid & 3) * 8;      // 0,8,16,24

    #pragma unroll 1
    for (int k0 = 0; k0 < NTOK; k0 += 64) {
        __syncthreads();
        {
            size_t ko = qkbase + (size_t)(k0 + lr) * HW + wo;
            *(uint4*)&Kh[lr * 36 + wo]     = *(const uint4*)(d_kh2 + ko);
            *(uint4*)&Kh[lr * 36 + wo + 4] = *(const uint4*)(d_kh2 + ko + 4);
            *(uint4*)&Kl[lr * 36 + wo]     = *(const uint4*)(d_kl2 + ko);
            *(uint4*)&Kl[lr * 36 + wo + 4] = *(const uint4*)(d_kl2 + ko + 4);
            size_t vo = vbase + (size_t)lr * NTOK + k0 + 2 * wo;
            *(uint4*)&Vh[lr * 36 + wo]     = *(const uint4*)(d_vth + vo);
            *(uint4*)&Vh[lr * 36 + wo + 4] = *(const uint4*)(d_vth + vo + 8);
            *(uint4*)&Vl[lr * 36 + wo]     = *(const uint4*)(d_vtl + vo);
            *(uint4*)&Vl[lr * 36 + wo + 4] = *(const uint4*)(d_vtl + vo + 8);
        }
        if (tid < 64) gk[tid] = d_g[b * NTOK + k0 + tid];
        __syncthreads();

        // S = Q K^T (hi/lo split, 3 MMAs per 16x8x16)
        float s[8][4];
        #pragma unroll
        for (int nf = 0; nf < 8; nf++)
            #pragma unroll
            for (int r = 0; r < 4; r++) s[nf][r] = 0.0f;
        #pragma unroll
        for (int s8 = 0; s8 < 4; s8++) {
            unsigned ah0 = Qh[rm * 36 + s8 * 8 + tg];
            unsigned ah1 = Qh[(rm + 8) * 36 + s8 * 8 + tg];
            unsigned ah2 = Qh[rm * 36 + s8 * 8 + 4 + tg];
            unsigned ah3 = Qh[(rm + 8) * 36 + s8 * 8 + 4 + tg];
            unsigned al0 = Ql[rm * 36 + s8 * 8 + tg];
            unsigned al1 = Ql[(rm + 8) * 36 + s8 * 8 + tg];
            unsigned al2 = Ql[rm * 36 + s8 * 8 + 4 + tg];
            unsigned al3 = Ql[(rm + 8) * 36 + s8 * 8 + 4 + tg];
            #pragma unroll
            for (int nf = 0; nf < 8; nf++) {
                int cn = nf * 8 + g;
                unsigned bh0 = Kh[cn * 36 + s8 * 8 + tg];
                unsigned bh1 = Kh[cn * 36 + s8 * 8 + 4 + tg];
                unsigned bl0 = Kl[cn * 36 + s8 * 8 + tg];
                unsigned bl1 = Kl[cn * 36 + s8 * 8 + 4 + tg];
                mma16(s[nf], ah0, ah1, ah2, ah3, bh0, bh1);
                mma16(s[nf], ah0, ah1, ah2, ah3, bl0, bl1);
                mma16(s[nf], al0, al1, al2, al3, bh0, bh1);
            }
        }

        // scale + gaussian bias + register softmax (4-lane shfl reductions)
        float gq0 = gq[rm], gq1 = gq[rm + 8];
        float mx0 = -CUDART_INF_F, mx1 = -CUDART_INF_F;
        #pragma unroll
        for (int nf = 0; nf < 8; nf++) {
            int c0 = nf * 8 + 2 * tg;
            float gk0 = gk[c0], gk1 = gk[c0 + 1];
            s[nf][0] = s[nf][0] * 0.125f + lam * gq0 * gk0;
            s[nf][1] = s[nf][1] * 0.125f + lam * gq0 * gk1;
            s[nf][2] = s[nf][2] * 0.125f + lam * gq1 * gk0;
            s[nf][3] = s[nf][3] * 0.125f + lam * gq1 * gk1;
            mx0 = fmaxf(mx0, fmaxf(s[nf][0], s[nf][1]));
            mx1 = fmaxf(mx1, fmaxf(s[nf][2], s[nf][3]));
        }
        mx0 = fmaxf(mx0, __shfl_xor_sync(0xffffffffu, mx0, 1));
        mx0 = fmaxf(mx0, __shfl_xor_sync(0xffffffffu, mx0, 2));
        mx1 = fmaxf(mx1, __shfl_xor_sync(0xffffffffu, mx1, 1));
        mx1 = fmaxf(mx1, __shfl_xor_sync(0xffffffffu, mx1, 2));

        float mn0 = fmaxf(m0, mx0), mn1 = fmaxf(m1, mx1);
        float alpha0 = __expf(m0 - mn0), alpha1 = __expf(m1 - mn1);
        m0 = mn0; m1 = mn1;

        float sum0 = 0.0f, sum1 = 0.0f;
        #pragma unroll
        for (int nf = 0; nf < 8; nf++) {
            s[nf][0] = __expf(s[nf][0] - mn0);
            s[nf][1] = __expf(s[nf][1] - mn0);
            s[nf][2] = __expf(s[nf][2] - mn1);
            s[nf][3] = __expf(s[nf][3] - mn1);
            sum0 += s[nf][0] + s[nf][1];
            sum1 += s[nf][2] + s[nf][3];
        }
        sum0 += __shfl_xor_sync(0xffffffffu, sum0, 1);
        sum0 += __shfl_xor_sync(0xffffffffu, sum0, 2);
        sum1 += __shfl_xor_sync(0xffffffffu, sum1, 1);
        sum1 += __shfl_xor_sync(0xffffffffu, sum1, 2);
        l0 = l0 * alpha0 + sum0;
        l1 = l1 * alpha1 + sum1;

        // rescale accumulator
        #pragma unroll
        for (int nf = 0; nf < 8; nf++) {
            o[nf][0] *= alpha0; o[nf][1] *= alpha0;
            o[nf][2] *= alpha1; o[nf][3] *= alpha1;
        }

        // O += P V : P A-fragments straight from the S register fragment
        #pragma unroll
        for (int s8 = 0; s8 < 4; s8++) {
            unsigned ah0, al0, ah1, al1, ah2, al2, ah3, al3;
            splitpack(s[2*s8][0],   s[2*s8][1],   ah0, al0);   // row g,   c 16s8+2tg
            splitpack(s[2*s8][2],   s[2*s8][3],   ah1, al1);   // row g+8
            splitpack(s[2*s8+1][0], s[2*s8+1][1], ah2, al2);   // row g,   c +8
            splitpack(s[2*s8+1][2], s[2*s8+1][3], ah3, al3);   // row g+8
            #pragma unroll
            for (int nf = 0; nf < 8; nf++) {
                int cn = nf * 8 + g;          // d index
                unsigned bh0 = Vh[cn * 36 + s8 * 8 + tg];
                unsigned bh1 = Vh[cn * 36 + s8 * 8 + 4 + tg];
                unsigned bl0 = Vl[cn * 36 + s8 * 8 + tg];
                unsigned bl1 = Vl[cn * 36 + s8 * 8 + 4 + tg];
                mma16(o[nf], ah0, ah1, ah2, ah3, bh0, bh1);
                mma16(o[nf], ah0, ah1, ah2, ah3, bl0, bl1);
                mma16(o[nf], al0, al1, al2, al3, bh0, bh1);
            }
        }
    }

    // normalize, split, write
    {
        float li0 = 1.0f / l0, li1 = 1.0f / l1;
        #pragma unroll
        for (int nf = 0; nf < 8; nf++) {
            int j = nf * 8 + 2 * tg;
            unsigned hw, lw;
            size_t w0 = ((size_t)b * NTOK + n0 + rm) * KW + ((h * HD + j) >> 1);
            splitpack(o[nf][0] * li0, o[nf][1] * li0, hw, lw);
            d_ath[w0] = hw; d_atl[w0] = lw;
            size_t w1 = ((size_t)b * NTOK + n0 + rm + 8) * KW + ((h * HD + j) >> 1);
            splitpack(o[nf][2] * li1, o[nf][3] * li1, hw, lw);
            d_ath[w1] = hw; d_atl[w1] = lw;
        }
    }
}

// ---------------- launch ----------------------------------------------------------
extern "C" void kernel_launch(void* const* d_in, const int* in_sizes, int n_in,
                              void* d_out, int out_size) {
    const float* feat = (const float*)d_in[0];
    const float* I    = (const float*)d_in[1];
    const float* pw   = (const float*)d_in[2];
    const float* pb   = (const float*)d_in[3];
    const float* wq   = (const float*)d_in[4];
    const float* bq   = (const float*)d_in[5];
    const float* wk   = (const float*)d_in[6];
    const float* bk   = (const float*)d_in[7];
    const float* wv   = (const float*)d_in[8];
    const float* bv   = (const float*)d_in[9];
    const float* wo   = (const float*)d_in[10];
    const float* bo   = (const float*)d_in[11];
    const float* lam  = (const float*)d_in[12];
    float* out = (float*)d_out;

    unsigned *tokh, *tokl, *ath, *atl, *fth, *ftl, *pwh, *pwl;
    unsigned *wqh, *wql, *wkh, *wkl, *wvh, *wvl, *woh, *wol;
    unsigned *qh2, *ql2, *kh2, *kl2;
    unsigned short *vth, *vtl;
    cudaGetSymbolAddress((void**)&tokh, d_tokh);
    cudaGetSymbolAddress((void**)&tokl, d_tokl);
    cudaGetSymbolAddress((void**)&ath,  d_ath);
    cudaGetSymbolAddress((void**)&atl,  d_atl);
    cudaGetSymbolAddress((void**)&fth,  d_fth);
    cudaGetSymbolAddress((void**)&ftl,  d_ftl);
    cudaGetSymbolAddress((void**)&pwh,  d_pwh);
    cudaGetSymbolAddress((void**)&pwl,  d_pwl);
    cudaGetSymbolAddress((void**)&wqh,  d_wqh);
    cudaGetSymbolAddress((void**)&wql,  d_wql);
    cudaGetSymbolAddress((void**)&wkh,  d_wkh);
    cudaGetSymbolAddress((void**)&wkl,  d_wkl);
    cudaGetSymbolAddress((void**)&wvh,  d_wvh);
    cudaGetSymbolAddress((void**)&wvl,  d_wvl);
    cudaGetSymbolAddress((void**)&woh,  d_woh);
    cudaGetSymbolAddress((void**)&wol,  d_wol);
    cudaGetSymbolAddress((void**)&qh2,  d_qh2);
    cudaGetSymbolAddress((void**)&ql2,  d_ql2);
    cudaGetSymbolAddress((void**)&kh2,  d_kh2);
    cudaGetSymbolAddress((void**)&kl2,  d_kl2);
    cudaGetSymbolAddress((void**)&vth,  d_vth);
    cudaGetSymbolAddress((void**)&vtl,  d_vtl);

    dim3 wsb(32, 8);
    // launches ordered so ncu (-s 5 -c 1) profiles launch #6 = gemm Q
    pe_kernel<<<(NTOK * HIDDEN + 255) / 256, 256>>>();                       // 1
    fsplit_kernel<<<dim3(NTOK / 32, C_IN / 32, BATCH), wsb>>>(               // 2
        feat, (unsigned short*)fth, (unsigned short*)ftl);
    wsplitg_kernel<<<dim3(HIDDEN / 32, C_IN / 32), wsb>>>(                   // 3
        pw, (unsigned short*)pwh, (unsigned short*)pwl, C_IN, HIDDEN);
    wsplit4_kernel<<<dim3(HIDDEN / 32, HIDDEN / 32, 4), wsb>>>(              // 4
        wq, wk, wv, wo,
        (unsigned short*)wqh, (unsigned short*)wql,
        (unsigned short*)wkh, (unsigned short*)wkl,
        (unsigned short*)wvh, (unsigned short*)wvl,
        (unsigned short*)woh, (unsigned short*)wol);

    dim3 gBig(HIDDEN / 128, M_TOT / 128);
    gemm_bf16<3, CW><<<gBig, 256>>>(fth, ftl, pwh, pwl, pb, nullptr,         // 5
                                    tokh, tokl, nullptr, nullptr);
    gemm_bf16<1, KW><<<gBig, 256>>>(tokh, tokl, wqh, wql, bq, nullptr,       // 6 <- profiled
                                    qh2, ql2, nullptr, nullptr);
    gemm_bf16<1, KW><<<gBig, 256>>>(tokh, tokl, wkh, wkl, bk, nullptr,       // 7
                                    kh2, kl2, nullptr, nullptr);
    gemm_bf16<2, KW><<<gBig, 256>>>(tokh, tokl, wvh, wvl, bv, nullptr,       // 8
                                    nullptr, nullptr, vth, vtl);
    gauss_kernel<<<(M_TOT + 255) / 256, 256>>>(I);                           // 9

    size_t smem = (2 * 128 * 36 + 4 * 64 * 36 + 128 + 64) * 4;  // 74496 B
    cudaFuncSetAttribute(attn_mma, cudaFuncAttributeMaxDynamicSharedMemorySize,
                         (int)smem);
    attn_mma<<<dim3(NTOK / 128, NHEAD, BATCH), 256, smem>>>(lam);            // 10

    gemm_bf16<0, KW><<<gBig, 256>>>(ath, atl, woh, wol, bo, out,             // 11
                                    nullptr, nullptr, nullptr, nullptr);
}

// round 16
// speedup vs baseline: 2.4788x; 1.0730x over previous
#include <cuda_runtime.h>
#include <cuda_bf16.h>
#include <math.h>
#include <math_constants.h>

#define HIDDEN 768
#define NHEAD  12
#define HD     64
#define BATCH  8
#define NTOK   1024
#define C_IN   256
#define M_TOT  (BATCH * NTOK)
#define KW     384            // HIDDEN/2 words (bf16x2 along k)
#define CW     128            // C_IN/2 words
#define HW     32             // HD/2 words per head-row

// ---------------- scratch (static device arrays; no allocation) ----------------
__device__ float d_g[M_TOT];
__device__ float d_pe[NTOK * HIDDEN];
__device__ unsigned d_tokh[M_TOT * KW];
__device__ unsigned d_tokl[M_TOT * KW];
__device__ unsigned d_ath[M_TOT * KW];
__device__ unsigned d_atl[M_TOT * KW];
__device__ unsigned d_fth[M_TOT * CW];
__device__ unsigned d_ftl[M_TOT * CW];
__device__ unsigned d_qh2[BATCH * NHEAD * NTOK * HW];
__device__ unsigned d_ql2[BATCH * NHEAD * NTOK * HW];
__device__ unsigned d_kh2[BATCH * NHEAD * NTOK * HW];
__device__ unsigned d_kl2[BATCH * NHEAD * NTOK * HW];
__device__ unsigned short d_vth[BATCH * NHEAD * HD * NTOK];
__device__ unsigned short d_vtl[BATCH * NHEAD * HD * NTOK];
__device__ unsigned d_pwh[HIDDEN * CW];
__device__ unsigned d_pwl[HIDDEN * CW];
__device__ unsigned d_wqh[HIDDEN * KW];
__device__ unsigned d_wql[HIDDEN * KW];
__device__ unsigned d_wkh[HIDDEN * KW];
__device__ unsigned d_wkl[HIDDEN * KW];
__device__ unsigned d_wvh[HIDDEN * KW];
__device__ unsigned d_wvl[HIDDEN * KW];
__device__ unsigned d_woh[HIDDEN * KW];
__device__ unsigned d_wol[HIDDEN * KW];

// ---------------- helpers --------------------------------------------------------
__device__ __forceinline__ void splitpack(float x0, float x1, unsigned& h, unsigned& l) {
    __nv_bfloat16 h0 = __float2bfloat16_rn(x0), h1 = __float2bfloat16_rn(x1);
    float r0 = x0 - __bfloat162float(h0), r1 = x1 - __bfloat162float(h1);
    __nv_bfloat16 l0 = __float2bfloat16_rn(r0), l1 = __float2bfloat16_rn(r1);
    h = ((unsigned)__bfloat16_as_ushort(h1) << 16) | (unsigned)__bfloat16_as_ushort(h0);
    l = ((unsigned)__bfloat16_as_ushort(l1) << 16) | (unsigned)__bfloat16_as_ushort(l0);
}
__device__ __forceinline__ void split1(float x, unsigned short& h, unsigned short& l) {
    __nv_bfloat16 hb = __float2bfloat16_rn(x);
    __nv_bfloat16 lb = __float2bfloat16_rn(x - __bfloat162float(hb));
    h = __bfloat16_as_ushort(hb);
    l = __bfloat16_as_ushort(lb);
}

__device__ __forceinline__ void mma16(float* c, unsigned a0, unsigned a1,
                                      unsigned a2, unsigned a3,
                                      unsigned b0, unsigned b1) {
    asm volatile(
        "mma.sync.aligned.m16n8k16.row.col.f32.bf16.bf16.f32 "
        "{%0,%1,%2,%3}, {%4,%5,%6,%7}, {%8,%9}, {%0,%1,%2,%3};"
        : "+f"(c[0]), "+f"(c[1]), "+f"(c[2]), "+f"(c[3])
        : "r"(a0), "r"(a1), "r"(a2), "r"(a3), "r"(b0), "r"(b1));
}

// ---------------- positional encoding -------------------------------------------
__global__ void pe_kernel() {
    int idx = blockIdx.x * blockDim.x + threadIdx.x;
    if (idx >= NTOK * HIDDEN) return;
    int n = idx / HIDDEN, d = idx % HIDDEN;
    int i2 = d & ~1;
    float div = expf((float)i2 * -0.011992630692677323f);  // -ln(10000)/768
    float ph = (float)n * div;
    d_pe[idx] = (d & 1) ? cosf(ph) : sinf(ph);
}

// ---------------- gaussian weights -----------------------------------------------
__global__ void gauss_kernel(const float* __restrict__ I) {
    int idx = blockIdx.x * blockDim.x + threadIdx.x;
    if (idx >= M_TOT) return;
    float x = I[idx];
    float x2 = x * x;
    const float d0 = 2.0f * 0.25f + 1e-5f;
    const float d1 = 2.0f * 1.00f + 1e-5f;
    const float d2 = 2.0f * 4.00f + 1e-5f;
    float g = (expf(-x2 / d0) + expf(-x2 / d1) + expf(-x2 / d2)) * (1.0f / 3.0f);
    d_g[idx] = g;
}

// ------------- generic weight transpose + split (single) --------------------------
__global__ void wsplitg_kernel(const float* __restrict__ W,
                               unsigned short* __restrict__ Th,
                               unsigned short* __restrict__ Tl,
                               int Kdim, int Ndim) {
    __shared__ float tile[32][33];
    int tx = threadIdx.x, ty = threadIdx.y;      // 32 x 8
    int n0 = blockIdx.x * 32, k0 = blockIdx.y * 32;
    #pragma unroll
    for (int r = 0; r < 32; r += 8)
        tile[ty + r][tx] = W[(size_t)(k0 + ty + r) * Ndim + n0 + tx];
    __syncthreads();
    #pragma unroll
    for (int r = 0; r < 32; r += 8) {
        float x = tile[tx][ty + r];
        unsigned short hs, ls;
        split1(x, hs, ls);
        size_t o = (size_t)(n0 + ty + r) * Kdim + k0 + tx;
        Th[o] = hs;
        Tl[o] = ls;
    }
}

// ------------- fused 4-way weight transpose + split (768x768, z selects weight) ---
__global__ void wsplit4_kernel(const float* __restrict__ w0, const float* __restrict__ w1,
                               const float* __restrict__ w2, const float* __restrict__ w3) {
    __shared__ float tile[32][33];
    int z = blockIdx.z;
    const float* W = (z == 0) ? w0 : (z == 1) ? w1 : (z == 2) ? w2 : w3;
    unsigned short* Th = (unsigned short*)((z == 0) ? d_wqh : (z == 1) ? d_wkh
                                           : (z == 2) ? d_wvh : d_woh);
    unsigned short* Tl = (unsigned short*)((z == 0) ? d_wql : (z == 1) ? d_wkl
                                           : (z == 2) ? d_wvl : d_wol);
    int tx = threadIdx.x, ty = threadIdx.y;
    int n0 = blockIdx.x * 32, k0 = blockIdx.y * 32;
    #pragma unroll
    for (int r = 0; r < 32; r += 8)
        tile[ty + r][tx] = W[(size_t)(k0 + ty + r) * HIDDEN + n0 + tx];
    __syncthreads();
    #pragma unroll
    for (int r = 0; r < 32; r += 8) {
        float x = tile[tx][ty + r];
        unsigned short hs, ls;
        split1(x, hs, ls);
        size_t o = (size_t)(n0 + ty + r) * HIDDEN + k0 + tx;
        Th[o] = hs;
        Tl[o] = ls;
    }
}

// ------------- feat transpose + split ---------------------------------------------
__global__ void fsplit_kernel(const float* __restrict__ feat) {
    __shared__ float tile[32][33];
    unsigned short* Fh = (unsigned short*)d_fth;
    unsigned short* Fl = (unsigned short*)d_ftl;
    int tx = threadIdx.x, ty = threadIdx.y;
    int n0 = blockIdx.x * 32, c0 = blockIdx.y * 32, b = blockIdx.z;
    const float* fb = feat + (size_t)b * C_IN * NTOK;
    #pragma unroll
    for (int r = 0; r < 32; r += 8)
        tile[ty + r][tx] = fb[(size_t)(c0 + ty + r) * NTOK + n0 + tx];
    __syncthreads();
    #pragma unroll
    for (int r = 0; r < 32; r += 8) {
        float x = tile[tx][ty + r];
        unsigned short hs, ls;
        split1(x, hs, ls);
        size_t o = ((size_t)b * NTOK + n0 + ty + r) * C_IN + c0 + tx;
        Fh[o] = hs;
        Fl[o] = ls;
    }
}

// ================= shared GEMM mainloop (macro-free via inline fn) ================
// Computes acc[4][4][4] for a 128x128 tile of (Ah+Al)@(Bh+Bl)^T.
template <int KWORDS>
__device__ __forceinline__ void gemm_mainloop(
    const unsigned* __restrict__ Ah, const unsigned* __restrict__ Al,
    const unsigned* __restrict__ Bh, const unsigned* __restrict__ Bl,
    int m0, int n0, int tid, float acc[4][4][4],
    unsigned (*Ahs)[128][9], unsigned (*Als)[128][9],
    unsigned (*Bhs)[128][9], unsigned (*Bls)[128][9]) {
    const int lane = tid & 31, wid = tid >> 5;
    const int wm = wid & 1, wn = wid >> 1;
    const int g = lane >> 2, tg = lane & 3;
    const int lr = tid >> 1;
    const int lh = (tid & 1) * 4;

    const unsigned* ApH = Ah + (size_t)(m0 + lr) * KWORDS + lh;
    const unsigned* ApL = Al + (size_t)(m0 + lr) * KWORDS + lh;
    const unsigned* BpH = Bh + (size_t)(n0 + lr) * KWORDS + lh;
    const unsigned* BpL = Bl + (size_t)(n0 + lr) * KWORDS + lh;

    uint4 rah = *(const uint4*)ApH, ral = *(const uint4*)ApL;
    uint4 rbh = *(const uint4*)BpH, rbl = *(const uint4*)BpL;

    Ahs[0][lr][lh+0]=rah.x; Ahs[0][lr][lh+1]=rah.y; Ahs[0][lr][lh+2]=rah.z; Ahs[0][lr][lh+3]=rah.w;
    Als[0][lr][lh+0]=ral.x; Als[0][lr][lh+1]=ral.y; Als[0][lr][lh+2]=ral.z; Als[0][lr][lh+3]=ral.w;
    Bhs[0][lr][lh+0]=rbh.x; Bhs[0][lr][lh+1]=rbh.y; Bhs[0][lr][lh+2]=rbh.z; Bhs[0][lr][lh+3]=rbh.w;
    Bls[0][lr][lh+0]=rbl.x; Bls[0][lr][lh+1]=rbl.y; Bls[0][lr][lh+2]=rbl.z; Bls[0][lr][lh+3]=rbl.w;

    const int NSLAB = KWORDS / 8;
    int buf = 0;
    #pragma unroll 1
    for (int t = 0; t < NSLAB; t++) {
        if (t < NSLAB - 1) {
            rah = *(const uint4*)(ApH + (t + 1) * 8);
            ral = *(const uint4*)(ApL + (t + 1) * 8);
            rbh = *(const uint4*)(BpH + (t + 1) * 8);
            rbl = *(const uint4*)(BpL + (t + 1) * 8);
        }
        __syncthreads();

        unsigned bh0[4], bh1[4], bl0[4], bl1[4];
        #pragma unroll
        for (int nf = 0; nf < 4; nf++) {
            int cn = wn * 32 + nf * 8 + g;
            bh0[nf] = Bhs[buf][cn][tg];   bh1[nf] = Bhs[buf][cn][tg + 4];
            bl0[nf] = Bls[buf][cn][tg];   bl1[nf] = Bls[buf][cn][tg + 4];
        }
        #pragma unroll
        for (int mf = 0; mf < 4; mf++) {
            int rm = wm * 64 + mf * 16 + g;
            unsigned ah0 = Ahs[buf][rm][tg],     ah1 = Ahs[buf][rm + 8][tg];
            unsigned ah2 = Ahs[buf][rm][tg + 4], ah3 = Ahs[buf][rm + 8][tg + 4];
            unsigned al0 = Als[buf][rm][tg],     al1 = Als[buf][rm + 8][tg];
            unsigned al2 = Als[buf][rm][tg + 4], al3 = Als[buf][rm + 8][tg + 4];
            #pragma unroll
            for (int nf = 0; nf < 4; nf++) {
                mma16(acc[mf][nf], ah0, ah1, ah2, ah3, bh0[nf], bh1[nf]);
                mma16(acc[mf][nf], ah0, ah1, ah2, ah3, bl0[nf], bl1[nf]);
                mma16(acc[mf][nf], al0, al1, al2, al3, bh0[nf], bh1[nf]);
            }
        }
        if (t < NSLAB - 1) {
            int nb = buf ^ 1;
            Ahs[nb][lr][lh+0]=rah.x; Ahs[nb][lr][lh+1]=rah.y; Ahs[nb][lr][lh+2]=rah.z; Ahs[nb][lr][lh+3]=rah.w;
            Als[nb][lr][lh+0]=ral.x; Als[nb][lr][lh+1]=ral.y; Als[nb][lr][lh+2]=ral.z; Als[nb][lr][lh+3]=ral.w;
            Bhs[nb][lr][lh+0]=rbh.x; Bhs[nb][lr][lh+1]=rbh.y; Bhs[nb][lr][lh+2]=rbh.z; Bhs[nb][lr][lh+3]=rbh.w;
            Bls[nb][lr][lh+0]=rbl.x; Bls[nb][lr][lh+1]=rbl.y; Bls[nb][lr][lh+2]=rbl.z; Bls[nb][lr][lh+3]=rbl.w;
        }
        buf ^= 1;
    }
}

// ================= standalone GEMM (MODE 0: fp32 out, MODE 3: tokens split) =======
template <int MODE, int KWORDS>
__global__ __launch_bounds__(256, 2)
void gemm_bf16(const unsigned* __restrict__ Ah, const unsigned* __restrict__ Al,
               const unsigned* __restrict__ Bh, const unsigned* __restrict__ Bl,
               const float* __restrict__ bias, float* __restrict__ Cout,
               unsigned* __restrict__ Ch, unsigned* __restrict__ Cl) {
    __shared__ unsigned Ahs[2][128][9], Als[2][128][9];
    __shared__ unsigned Bhs[2][128][9], Bls[2][128][9];
    const int tid = threadIdx.x;
    const int lane = tid & 31, wid = tid >> 5;
    const int wm = wid & 1, wn = wid >> 1;
    const int g = lane >> 2, tg = lane & 3;
    const int n0 = blockIdx.x * 128, m0 = blockIdx.y * 128;

    float acc[4][4][4];
    #pragma unroll
    for (int i = 0; i < 4; i++)
        #pragma unroll
        for (int j = 0; j < 4; j++)
            #pragma unroll
            for (int r = 0; r < 4; r++) acc[i][j][r] = 0.0f;

    gemm_mainloop<KWORDS>(Ah, Al, Bh, Bl, m0, n0, tid, acc, Ahs, Als, Bhs, Bls);

    #pragma unroll
    for (int mf = 0; mf < 4; mf++) {
        int r0 = m0 + wm * 64 + mf * 16 + g;
        #pragma unroll
        for (int nf = 0; nf < 4; nf++) {
            int j = n0 + wn * 32 + nf * 8 + 2 * tg;
            float v00 = acc[mf][nf][0] + bias[j];
            float v01 = acc[mf][nf][1] + bias[j + 1];
            float v10 = acc[mf][nf][2] + bias[j];
            float v11 = acc[mf][nf][3] + bias[j + 1];
            int r1 = r0 + 8;
            if (MODE == 0) {
                *(float2*)&Cout[(size_t)r0 * HIDDEN + j] = make_float2(v00, v01);
                *(float2*)&Cout[(size_t)r1 * HIDDEN + j] = make_float2(v10, v11);
            } else {  // MODE 3: tokens = . + pb + pe, split
                const float* pe0 = d_pe + (size_t)(r0 & 1023) * HIDDEN + j;
                const float* pe1 = d_pe + (size_t)(r1 & 1023) * HIDDEN + j;
                unsigned hw, lw;
                splitpack(v00 + pe0[0], v01 + pe0[1], hw, lw);
                size_t w0 = (size_t)r0 * KW + (j >> 1);
                Ch[w0] = hw; Cl[w0] = lw;
                splitpack(v10 + pe1[0], v11 + pe1[1], hw, lw);
                size_t w1 = (size_t)r1 * KW + (j >> 1);
                Ch[w1] = hw; Cl[w1] = lw;
            }
        }
    }
}

// ================= fused QKV GEMM: gridDim.z selects {Q, K, V} ====================
__global__ __launch_bounds__(256, 2)
void gemm_qkv(const float* __restrict__ bq, const float* __restrict__ bk,
              const float* __restrict__ bv) {
    __shared__ unsigned Ahs[2][128][9], Als[2][128][9];
    __shared__ unsigned Bhs[2][128][9], Bls[2][128][9];
    const int tid = threadIdx.x;
    const int lane = tid & 31, wid = tid >> 5;
    const int wm = wid & 1, wn = wid >> 1;
    const int g = lane >> 2, tg = lane & 3;
    const int n0 = blockIdx.x * 128, m0 = blockIdx.y * 128;
    const int z = blockIdx.z;

    const unsigned* Bh = (z == 0) ? d_wqh : (z == 1) ? d_wkh : d_wvh;
    const unsigned* Bl = (z == 0) ? d_wql : (z == 1) ? d_wkl : d_wvl;
    const float* bias  = (z == 0) ? bq : (z == 1) ? bk : bv;

    float acc[4][4][4];
    #pragma unroll
    for (int i = 0; i < 4; i++)
        #pragma unroll
        for (int j = 0; j < 4; j++)
            #pragma unroll
            for (int r = 0; r < 4; r++) acc[i][j][r] = 0.0f;

    gemm_mainloop<KW>(d_tokh, d_tokl, Bh, Bl, m0, n0, tid, acc, Ahs, Als, Bhs, Bls);

    unsigned* Ch = (z == 0) ? d_qh2 : d_kh2;
    unsigned* Cl = (z == 0) ? d_ql2 : d_kl2;

    #pragma unroll
    for (int mf = 0; mf < 4; mf++) {
        int r0 = m0 + wm * 64 + mf * 16 + g;
        #pragma unroll
        for (int nf = 0; nf < 4; nf++) {
            int j = n0 + wn * 32 + nf * 8 + 2 * tg;
            float v00 = acc[mf][nf][0] + bias[j];
            float v01 = acc[mf][nf][1] + bias[j + 1];
            float v10 = acc[mf][nf][2] + bias[j];
            float v11 = acc[mf][nf][3] + bias[j + 1];
            int r1 = r0 + 8;
            int h = j >> 6;
            int b0i = r0 >> 10, nn0 = r0 & 1023;
            int b1i = r1 >> 10, nn1 = r1 & 1023;
            if (z < 2) {
                int w = (j & 63) >> 1;
                unsigned hw, lw;
                size_t i0 = ((size_t)(b0i * NHEAD + h) * NTOK + nn0) * HW + w;
                splitpack(v00, v01, hw, lw); Ch[i0] = hw; Cl[i0] = lw;
                size_t i1 = ((size_t)(b1i * NHEAD + h) * NTOK + nn1) * HW + w;
                splitpack(v10, v11, hw, lw); Ch[i1] = hw; Cl[i1] = lw;
            } else {
                int dd = j & 63;
                unsigned short hs, ls;
                size_t base0 = ((size_t)(b0i * NHEAD + h) * HD + dd) * NTOK;
                size_t base1 = ((size_t)(b1i * NHEAD + h) * HD + dd) * NTOK;
                split1(v00, hs, ls); d_vth[base0 + nn0]        = hs; d_vtl[base0 + nn0]        = ls;
                split1(v01, hs, ls); d_vth[base0 + NTOK + nn0] = hs; d_vtl[base0 + NTOK + nn0] = ls;
                split1(v10, hs, ls); d_vth[base1 + nn1]        = hs; d_vtl[base1 + nn1]        = ls;
                split1(v11, hs, ls); d_vth[base1 + NTOK + nn1] = hs; d_vtl[base1 + NTOK + nn1] = ls;
            }
        }
    }
}

// ================= flash attention: 128-row q-tile, P & softmax in registers =====
__global__ __launch_bounds__(256)
void attn_mma(const float* __restrict__ lam_p) {
    extern __shared__ unsigned smw[];
    unsigned* Qh = smw;                   // [128][36]
    unsigned* Ql = Qh + 128 * 36;
    unsigned* Kh = Ql + 128 * 36;         // [64][36]  (row=c, word=d)
    unsigned* Kl = Kh + 64 * 36;
    unsigned* Vh = Kl + 64 * 36;          // V^T: [64][36] (row=d, word=c)
    unsigned* Vl = Vh + 64 * 36;
    float* gq = (float*)(Vl + 64 * 36);   // [128]
    float* gk = gq + 128;                 // [64]

    const int tid = threadIdx.x;
    const int lane = tid & 31, wm = tid >> 5;
    const int g = lane >> 2, tg = lane & 3;
    const int n0 = blockIdx.x * 128;
    const int h = blockIdx.y, b = blockIdx.z;
    const float lam = *lam_p;
    const int rm = wm * 16 + g;

    const size_t qkbase = (size_t)(b * NHEAD + h) * NTOK * HW;
    const size_t vbase  = (size_t)(b * NHEAD + h) * HD * NTOK;

    {
        int lr = tid >> 1, w0 = (tid & 1) * 16;
        size_t o = qkbase + (size_t)(n0 + lr) * HW + w0;
        #pragma unroll
        for (int i = 0; i < 16; i += 4) {
            *(uint4*)&Qh[lr * 36 + w0 + i] = *(const uint4*)(d_qh2 + o + i);
            *(uint4*)&Ql[lr * 36 + w0 + i] = *(const uint4*)(d_ql2 + o + i);
        }
    }
    if (tid < 128) gq[tid] = d_g[b * NTOK + n0 + tid];

    float m0 = -CUDART_INF_F, m1 = -CUDART_INF_F;
    float l0 = 0.0f, l1 = 0.0f;
    float o[8][4];
    #pragma unroll
    for (int nf = 0; nf < 8; nf++)
        #pragma unroll
        for (int r = 0; r < 4; r++) o[nf][r] = 0.0f;

    const int lr = tid >> 2;
    const int wo = (tid & 3) * 8;

    #pragma unroll 1
    for (int k0 = 0; k0 < NTOK; k0 += 64) {
        __syncthreads();
        {
            size_t ko = qkbase + (size_t)(k0 + lr) * HW + wo;
            *(uint4*)&Kh[lr * 36 + wo]     = *(const uint4*)(d_kh2 + ko);
            *(uint4*)&Kh[lr * 36 + wo + 4] = *(const uint4*)(d_kh2 + ko + 4);
            *(uint4*)&Kl[lr * 36 + wo]     = *(const uint4*)(d_kl2 + ko);
            *(uint4*)&Kl[lr * 36 + wo + 4] = *(const uint4*)(d_kl2 + ko + 4);
            size_t vo = vbase + (size_t)lr * NTOK + k0 + 2 * wo;
            *(uint4*)&Vh[lr * 36 + wo]     = *(const uint4*)(d_vth + vo);
            *(uint4*)&Vh[lr * 36 + wo + 4] = *(const uint4*)(d_vth + vo + 8);
            *(uint4*)&Vl[lr * 36 + wo]     = *(const uint4*)(d_vtl + vo);
            *(uint4*)&Vl[lr * 36 + wo + 4] = *(const uint4*)(d_vtl + vo + 8);
        }
        if (tid < 64) gk[tid] = d_g[b * NTOK + k0 + tid];
        __syncthreads();

        float s[8][4];
        #pragma unroll
        for (int nf = 0; nf < 8; nf++)
            #pragma unroll
            for (int r = 0; r < 4; r++) s[nf][r] = 0.0f;
        #pragma unroll
        for (int s8 = 0; s8 < 4; s8++) {
            unsigned ah0 = Qh[rm * 36 + s8 * 8 + tg];
            unsigned ah1 = Qh[(rm + 8) * 36 + s8 * 8 + tg];
            unsigned ah2 = Qh[rm * 36 + s8 * 8 + 4 + tg];
            unsigned ah3 = Qh[(rm + 8) * 36 + s8 * 8 + 4 + tg];
            unsigned al0 = Ql[rm * 36 + s8 * 8 + tg];
            unsigned al1 = Ql[(rm + 8) * 36 + s8 * 8 + tg];
            unsigned al2 = Ql[rm * 36 + s8 * 8 + 4 + tg];
            unsigned al3 = Ql[(rm + 8) * 36 + s8 * 8 + 4 + tg];
            #pragma unroll
            for (int nf = 0; nf < 8; nf++) {
                int cn = nf * 8 + g;
                unsigned bh0 = Kh[cn * 36 + s8 * 8 + tg];
                unsigned bh1 = Kh[cn * 36 + s8 * 8 + 4 + tg];
                unsigned bl0 = Kl[cn * 36 + s8 * 8 + tg];
                unsigned bl1 = Kl[cn * 36 + s8 * 8 + 4 + tg];
                mma16(s[nf], ah0, ah1, ah2, ah3, bh0, bh1);
                mma16(s[nf], ah0, ah1, ah2, ah3, bl0, bl1);
                mma16(s[nf], al0, al1, al2, al3, bh0, bh1);
            }
        }

        float gq0 = gq[rm], gq1 = gq[rm + 8];
        float mx0 = -CUDART_INF_F, mx1 = -CUDART_INF_F;
        #pragma unroll
        for (int nf = 0; nf < 8; nf++) {
            int c0 = nf * 8 + 2 * tg;
            float gk0 = gk[c0], gk1 = gk[c0 + 1];
            s[nf][0] = s[nf][0] * 0.125f + lam * gq0 * gk0;
            s[nf][1] = s[nf][1] * 0.125f + lam * gq0 * gk1;
            s[nf][2] = s[nf][2] * 0.125f + lam * gq1 * gk0;
            s[nf][3] = s[nf][3] * 0.125f + lam * gq1 * gk1;
            mx0 = fmaxf(mx0, fmaxf(s[nf][0], s[nf][1]));
            mx1 = fmaxf(mx1, fmaxf(s[nf][2], s[nf][3]));
        }
        mx0 = fmaxf(mx0, __shfl_xor_sync(0xffffffffu, mx0, 1));
        mx0 = fmaxf(mx0, __shfl_xor_sync(0xffffffffu, mx0, 2));
        mx1 = fmaxf(mx1, __shfl_xor_sync(0xffffffffu, mx1, 1));
        mx1 = fmaxf(mx1, __shfl_xor_sync(0xffffffffu, mx1, 2));

        float mn0 = fmaxf(m0, mx0), mn1 = fmaxf(m1, mx1);
        float alpha0 = __expf(m0 - mn0), alpha1 = __expf(m1 - mn1);
        m0 = mn0; m1 = mn1;

        float sum0 = 0.0f, sum1 = 0.0f;
        #pragma unroll
        for (int nf = 0; nf < 8; nf++) {
            s[nf][0] = __expf(s[nf][0] - mn0);
            s[nf][1] = __expf(s[nf][1] - mn0);
            s[nf][2] = __expf(s[nf][2] - mn1);
            s[nf][3] = __expf(s[nf][3] - mn1);
            sum0 += s[nf][0] + s[nf][1];
            sum1 += s[nf][2] + s[nf][3];
        }
        sum0 += __shfl_xor_sync(0xffffffffu, sum0, 1);
        sum0 += __shfl_xor_sync(0xffffffffu, sum0, 2);
        sum1 += __shfl_xor_sync(0xffffffffu, sum1, 1);
        sum1 += __shfl_xor_sync(0xffffffffu, sum1, 2);
        l0 = l0 * alpha0 + sum0;
        l1 = l1 * alpha1 + sum1;

        #pragma unroll
        for (int nf = 0; nf < 8; nf++) {
            o[nf][0] *= alpha0; o[nf][1] *= alpha0;
            o[nf][2] *= alpha1; o[nf][3] *= alpha1;
        }

        #pragma unroll
        for (int s8 = 0; s8 < 4; s8++) {
            unsigned ah0, al0, ah1, al1, ah2, al2, ah3, al3;
            splitpack(s[2*s8][0],   s[2*s8][1],   ah0, al0);
            splitpack(s[2*s8][2],   s[2*s8][3],   ah1, al1);
            splitpack(s[2*s8+1][0], s[2*s8+1][1], ah2, al2);
            splitpack(s[2*s8+1][2], s[2*s8+1][3], ah3, al3);
            #pragma unroll
            for (int nf = 0; nf < 8; nf++) {
                int cn = nf * 8 + g;
                unsigned bh0 = Vh[cn * 36 + s8 * 8 + tg];
                unsigned bh1 = Vh[cn * 36 + s8 * 8 + 4 + tg];
                unsigned bl0 = Vl[cn * 36 + s8 * 8 + tg];
                unsigned bl1 = Vl[cn * 36 + s8 * 8 + 4 + tg];
                mma16(o[nf], ah0, ah1, ah2, ah3, bh0, bh1);
                mma16(o[nf], ah0, ah1, ah2, ah3, bl0, bl1);
                mma16(o[nf], al0, al1, al2, al3, bh0, bh1);
            }
        }
    }

    {
        float li0 = 1.0f / l0, li1 = 1.0f / l1;
        #pragma unroll
        for (int nf = 0; nf < 8; nf++) {
            int j = nf * 8 + 2 * tg;
            unsigned hw, lw;
            size_t w0 = ((size_t)b * NTOK + n0 + rm) * KW + ((h * HD + j) >> 1);
            splitpack(o[nf][0] * li0, o[nf][1] * li0, hw, lw);
            d_ath[w0] = hw; d_atl[w0] = lw;
            size_t w1 = ((size_t)b * NTOK + n0 + rm + 8) * KW + ((h * HD + j) >> 1);
            splitpack(o[nf][2] * li1, o[nf][3] * li1, hw, lw);
            d_ath[w1] = hw; d_atl[w1] = lw;
        }
    }
}

// ---------------- launch ----------------------------------------------------------
extern "C" void kernel_launch(void* const* d_in, const int* in_sizes, int n_in,
                              void* d_out, int out_size) {
    const float* feat = (const float*)d_in[0];
    const float* I    = (const float*)d_in[1];
    const float* pw   = (const float*)d_in[2];
    const float* pb   = (const float*)d_in[3];
    const float* wq   = (const float*)d_in[4];
    const float* bq   = (const float*)d_in[5];
    const float* wk   = (const float*)d_in[6];
    const float* bk   = (const float*)d_in[7];
    const float* wv   = (const float*)d_in[8];
    const float* bv   = (const float*)d_in[9];
    const float* wo   = (const float*)d_in[10];
    const float* bo   = (const float*)d_in[11];
    const float* lam  = (const float*)d_in[12];
    float* out = (float*)d_out;

    unsigned *tokh, *tokl, *ath, *atl, *fth, *ftl, *pwh, *pwl, *woh, *wol;
    cudaGetSymbolAddress((void**)&tokh, d_tokh);
    cudaGetSymbolAddress((void**)&tokl, d_tokl);
    cudaGetSymbolAddress((void**)&ath,  d_ath);
    cudaGetSymbolAddress((void**)&atl,  d_atl);
    cudaGetSymbolAddress((void**)&fth,  d_fth);
    cudaGetSymbolAddress((void**)&ftl,  d_ftl);
    cudaGetSymbolAddress((void**)&pwh,  d_pwh);
    cudaGetSymbolAddress((void**)&pwl,  d_pwl);
    cudaGetSymbolAddress((void**)&woh,  d_woh);
    cudaGetSymbolAddress((void**)&wol,  d_wol);

    dim3 wsb(32, 8);
    dim3 gBig(HIDDEN / 128, M_TOT / 128);
    dim3 gQKV(HIDDEN / 128, M_TOT / 128, 3);

    // order: positions 4 and 6 are both GEMMs (profiler lands on one of them)
    fsplit_kernel<<<dim3(NTOK / 32, C_IN / 32, BATCH), wsb>>>(feat);         // 1
    wsplitg_kernel<<<dim3(HIDDEN / 32, C_IN / 32), wsb>>>(                   // 2
        pw, (unsigned short*)pwh, (unsigned short*)pwl, C_IN, HIDDEN);
    pe_kernel<<<(NTOK * HIDDEN + 255) / 256, 256>>>();                       // 3
    gemm_bf16<3, CW><<<gBig, 256>>>(fth, ftl, pwh, pwl, pb, nullptr,         // 4 (GEMM)
                                    tokh, tokl);
    wsplit4_kernel<<<dim3(HIDDEN / 32, HIDDEN / 32, 4), wsb>>>(wq, wk, wv, wo); // 5
    gemm_qkv<<<gQKV, 256>>>(bq, bk, bv);                                     // 6 (GEMM)
    gauss_kernel<<<(M_TOT + 255) / 256, 256>>>(I);                           // 7

    size_t smem = (2 * 128 * 36 + 4 * 64 * 36 + 128 + 64) * 4;  // 74496 B
    cudaFuncSetAttribute(attn_mma, cudaFuncAttributeMaxDynamicSharedMemorySize,
                         (int)smem);
    attn_mma<<<dim3(NTOK / 128, NHEAD, BATCH), 256, smem>>>(lam);            // 8

    gemm_bf16<0, KW><<<gBig, 256>>>(ath, atl, woh, wol, bo, out,             // 9
                                    nullptr, nullptr);
}